// round 6
// baseline (speedup 1.0000x reference)
#include <cuda_runtime.h>
#include <math.h>
#include <stdint.h>

#define B_SZ 2
#define L 1024
#define D 384
#define PATCH_DIM 4096
#define DEPTH 12
#define DSTATE 16
#define DTRANK 24
#define DBL_N 56
#define NTOK (B_SZ * L)   // 2048
#define NCH 8             // scan chunks
#define CHL (L / NCH)     // 128 steps per chunk

typedef unsigned long long ull;

// ------------------------- scratch (static device) -------------------------
__device__ float g_tok[NTOK * D];
__device__ float g_h[NTOK * D];
__device__ float g_xz[NTOK * 2 * D];
__device__ float g_xc[NTOK * D];
__device__ float g_dbl[NTOK * DBL_N];
__device__ float g_y[NTOK * D];

// ------------------------- f32x2 helpers ------------------------------------
__device__ __forceinline__ ull pack2(float x, float y) {
    ull r; asm("mov.b64 %0, {%1, %2};" : "=l"(r) : "f"(x), "f"(y)); return r;
}
__device__ __forceinline__ void unpack2(ull v, float& x, float& y) {
    asm("mov.b64 {%0, %1}, %2;" : "=f"(x), "=f"(y) : "l"(v));
}
__device__ __forceinline__ void ffma2(ull& d, ull a, ull b) {
    asm("fma.rn.f32x2 %0, %1, %2, %0;" : "+l"(d) : "l"(a), "l"(b));
}

// ------------------------- SIMT GEMM: 64x64x16, 64 threads, 8x8 microtile --
// A smem is stored k-major (transposed) so compute reads are LDS.128.
// Double-buffered via register staging (LDG -> regs -> STS).
// epi: 0 none, 1 +bias, 3 C += result. gridDim.z>1 -> split-K atomicAdd.
#define GBM 64
#define GBN 64
#define GBK 16

struct GemmSmem {
    __align__(16) float As[2][GBK][GBM];
    __align__(16) float Bs[2][GBK][GBN];
};

__device__ __forceinline__ void gemm_compute(const float (*As)[GBM],
                                             const float (*Bs)[GBN],
                                             int ty, int tx, ull acc[4][8])
{
    #pragma unroll
    for (int kk = 0; kk < GBK; kk++) {
        float4 af0 = *reinterpret_cast<const float4*>(&As[kk][ty * 8]);
        float4 af1 = *reinterpret_cast<const float4*>(&As[kk][ty * 8 + 4]);
        float4 bf0 = *reinterpret_cast<const float4*>(&Bs[kk][tx * 8]);
        float4 bf1 = *reinterpret_cast<const float4*>(&Bs[kk][tx * 8 + 4]);
        ull ap[4];
        ap[0] = pack2(af0.x, af0.y); ap[1] = pack2(af0.z, af0.w);
        ap[2] = pack2(af1.x, af1.y); ap[3] = pack2(af1.z, af1.w);
        ull bd[8];
        bd[0] = pack2(bf0.x, bf0.x); bd[1] = pack2(bf0.y, bf0.y);
        bd[2] = pack2(bf0.z, bf0.z); bd[3] = pack2(bf0.w, bf0.w);
        bd[4] = pack2(bf1.x, bf1.x); bd[5] = pack2(bf1.y, bf1.y);
        bd[6] = pack2(bf1.z, bf1.z); bd[7] = pack2(bf1.w, bf1.w);
        #pragma unroll
        for (int i = 0; i < 4; i++)
            #pragma unroll
            for (int j = 0; j < 8; j++)
                ffma2(acc[i][j], ap[i], bd[j]);
    }
}

__global__ void sgemm_k(const float* __restrict__ A, int lda,
                        const float* __restrict__ Bm,
                        float* __restrict__ C,
                        const float* __restrict__ bias,
                        int M, int N, int K, int epi)
{
    __shared__ GemmSmem sm;
    const int bm = blockIdx.y * GBM, bn = blockIdx.x * GBN;
    const int t = threadIdx.x;                 // 64 threads
    const int tx = t & 7, ty = t >> 3;

    const int ksplit = gridDim.z;
    const int kc = K / ksplit;                  // multiple of 16 by caller
    const int kstart = blockIdx.z * kc;
    const int niters = kc / GBK;

    // loaders
    const float* Arow = A + (size_t)(bm + t) * lda + kstart;
    const int kb = t >> 2, cs = (t & 3) * 16;

    float4 aR[4], bR[4];
    auto ldA = [&](int it) {
        #pragma unroll
        for (int q = 0; q < 4; q++)
            aR[q] = *reinterpret_cast<const float4*>(Arow + it * GBK + q * 4);
    };
    auto ldB = [&](int it) {
        const float* Brow = Bm + (size_t)(kstart + it * GBK + kb) * N + bn + cs;
        #pragma unroll
        for (int q = 0; q < 4; q++) {
            int col = bn + cs + q * 4;
            bR[q] = (col < N) ? *reinterpret_cast<const float4*>(Brow + q * 4)
                              : make_float4(0.f, 0.f, 0.f, 0.f);
        }
    };
    auto stAB = [&](int buf) {
        #pragma unroll
        for (int q = 0; q < 4; q++) {
            sm.As[buf][q * 4 + 0][t] = aR[q].x;
            sm.As[buf][q * 4 + 1][t] = aR[q].y;
            sm.As[buf][q * 4 + 2][t] = aR[q].z;
            sm.As[buf][q * 4 + 3][t] = aR[q].w;
        }
        #pragma unroll
        for (int q = 0; q < 4; q++)
            *reinterpret_cast<float4*>(&sm.Bs[buf][kb][cs + q * 4]) = bR[q];
    };

    ull acc[4][8];
    #pragma unroll
    for (int i = 0; i < 4; i++)
        #pragma unroll
        for (int j = 0; j < 8; j++) acc[i][j] = 0ull;

    ldA(0); ldB(0); stAB(0);
    __syncthreads();

    for (int it = 0; it < niters; it++) {
        const int buf = it & 1;
        if (it + 1 < niters) { ldA(it + 1); ldB(it + 1); }
        gemm_compute(sm.As[buf], sm.Bs[buf], ty, tx, acc);
        __syncthreads();
        if (it + 1 < niters) { stAB(buf ^ 1); __syncthreads(); }
    }

    // epilogue: rows bm + ty*8 + 2i(+1), cols bn + tx*8 + j
    const int n0 = bn + tx * 8;
    if (ksplit > 1) {
        #pragma unroll
        for (int i = 0; i < 4; i++) {
            int r0 = bm + ty * 8 + 2 * i;
            #pragma unroll
            for (int j = 0; j < 8; j++) {
                float v0, v1; unpack2(acc[i][j], v0, v1);
                int col = n0 + j;
                if (col < N) {
                    atomicAdd(&C[(size_t)r0 * N + col], v0);
                    atomicAdd(&C[(size_t)(r0 + 1) * N + col], v1);
                }
            }
        }
    } else {
        #pragma unroll
        for (int i = 0; i < 4; i++) {
            float lo[8], hi[8];
            #pragma unroll
            for (int j = 0; j < 8; j++) unpack2(acc[i][j], lo[j], hi[j]);
            int r0 = bm + ty * 8 + 2 * i;
            float* C0 = C + (size_t)r0 * N + n0;
            float* C1 = C + (size_t)(r0 + 1) * N + n0;
            if (epi == 1) {
                #pragma unroll
                for (int j = 0; j < 8; j++) {
                    float bv = bias[n0 + j];
                    lo[j] += bv; hi[j] += bv;
                }
            } else if (epi == 3) {
                #pragma unroll
                for (int j = 0; j < 8; j += 4) {
                    float4 c0 = *reinterpret_cast<float4*>(C0 + j);
                    float4 c1 = *reinterpret_cast<float4*>(C1 + j);
                    lo[j] += c0.x; lo[j+1] += c0.y; lo[j+2] += c0.z; lo[j+3] += c0.w;
                    hi[j] += c1.x; hi[j+1] += c1.y; hi[j+2] += c1.z; hi[j+3] += c1.w;
                }
            }
            #pragma unroll
            for (int j = 0; j < 8; j += 4) {
                *reinterpret_cast<float4*>(C0 + j) = make_float4(lo[j], lo[j+1], lo[j+2], lo[j+3]);
                *reinterpret_cast<float4*>(C1 + j) = make_float4(hi[j], hi[j+1], hi[j+2], hi[j+3]);
            }
        }
    }
}

// ------------------------- patchify GEMM (im2col fused) --------------------
__global__ void sgemm_patch_k(const float* __restrict__ X,
                              const float* __restrict__ Bm,
                              float* __restrict__ C,
                              const float* __restrict__ bias)
{
    __shared__ GemmSmem sm;
    const int bm = blockIdx.y * GBM, bn = blockIdx.x * GBN;
    const int t = threadIdx.x;
    const int tx = t & 7, ty = t >> 3;
    const int N = D;
    const int niters = PATCH_DIM / GBK;

    const int m = bm + t;
    const int b = m >> 10, l = m & 1023;
    const int gh = l >> 6, gw = (l >> 3) & 7, gd = l & 7;
    const size_t xbase = ((size_t)(b * 256 + gh * 16) * 256 + gw * 32) * 64 + gd * 8;

    const int kb = t >> 2, cs = (t & 3) * 16;

    float4 aR[4], bR[4];
    auto ldA = [&](int it) {
        #pragma unroll
        for (int q = 0; q < 4; q++) {
            int k = it * GBK + q * 4;
            int ph = k >> 8, pw = (k >> 3) & 31, pd = k & 7;
            aR[q] = *reinterpret_cast<const float4*>(X + xbase + (size_t)ph * 16384 + pw * 64 + pd);
        }
    };
    auto ldB = [&](int it) {
        const float* Brow = Bm + (size_t)(it * GBK + kb) * N + bn + cs;
        #pragma unroll
        for (int q = 0; q < 4; q++)
            bR[q] = *reinterpret_cast<const float4*>(Brow + q * 4);
    };
    auto stAB = [&](int buf) {
        #pragma unroll
        for (int q = 0; q < 4; q++) {
            sm.As[buf][q * 4 + 0][t] = aR[q].x;
            sm.As[buf][q * 4 + 1][t] = aR[q].y;
            sm.As[buf][q * 4 + 2][t] = aR[q].z;
            sm.As[buf][q * 4 + 3][t] = aR[q].w;
        }
        #pragma unroll
        for (int q = 0; q < 4; q++)
            *reinterpret_cast<float4*>(&sm.Bs[buf][kb][cs + q * 4]) = bR[q];
    };

    ull acc[4][8];
    #pragma unroll
    for (int i = 0; i < 4; i++)
        #pragma unroll
        for (int j = 0; j < 8; j++) acc[i][j] = 0ull;

    ldA(0); ldB(0); stAB(0);
    __syncthreads();

    for (int it = 0; it < niters; it++) {
        const int buf = it & 1;
        if (it + 1 < niters) { ldA(it + 1); ldB(it + 1); }
        gemm_compute(sm.As[buf], sm.Bs[buf], ty, tx, acc);
        __syncthreads();
        if (it + 1 < niters) { stAB(buf ^ 1); __syncthreads(); }
    }

    const int n0 = bn + tx * 8;
    #pragma unroll
    for (int i = 0; i < 4; i++) {
        float lo[8], hi[8];
        #pragma unroll
        for (int j = 0; j < 8; j++) {
            unpack2(acc[i][j], lo[j], hi[j]);
            float bv = bias[n0 + j];
            lo[j] += bv; hi[j] += bv;
        }
        int r0 = bm + ty * 8 + 2 * i;
        float* C0 = C + (size_t)r0 * N + n0;
        float* C1 = C + (size_t)(r0 + 1) * N + n0;
        #pragma unroll
        for (int j = 0; j < 8; j += 4) {
            *reinterpret_cast<float4*>(C0 + j) = make_float4(lo[j], lo[j+1], lo[j+2], lo[j+3]);
            *reinterpret_cast<float4*>(C1 + j) = make_float4(hi[j], hi[j+1], hi[j+2], hi[j+3]);
        }
    }
}

// ------------------------- LayerNorm (row of 384) + dbl zeroing ------------
__global__ void ln_k(const float* __restrict__ in, float* __restrict__ out,
                     const float* __restrict__ w, const float* __restrict__ b,
                     float* __restrict__ zbuf)
{
    int row = blockIdx.x;
    int t = threadIdx.x;   // 128 threads
    if (zbuf != nullptr && t < DBL_N) zbuf[(size_t)row * DBL_N + t] = 0.f;
    const float* r = in + (size_t)row * D;
    float v0 = r[t], v1 = r[t + 128], v2 = r[t + 256];
    float s = v0 + v1 + v2;
    __shared__ float sh[4], sh2[4];
    #pragma unroll
    for (int o = 16; o; o >>= 1) s += __shfl_xor_sync(~0u, s, o);
    if ((t & 31) == 0) sh[t >> 5] = s;
    __syncthreads();
    float mu = (sh[0] + sh[1] + sh[2] + sh[3]) * (1.f / 384.f);
    float d0 = v0 - mu, d1 = v1 - mu, d2 = v2 - mu;
    float q = d0 * d0 + d1 * d1 + d2 * d2;
    #pragma unroll
    for (int o = 16; o; o >>= 1) q += __shfl_xor_sync(~0u, q, o);
    if ((t & 31) == 0) sh2[t >> 5] = q;
    __syncthreads();
    float var = (sh2[0] + sh2[1] + sh2[2] + sh2[3]) * (1.f / 384.f);
    float rs = rsqrtf(var + 1e-5f);
    float* o = out + (size_t)row * D;
    o[t]       = d0 * rs * w[t]       + b[t];
    o[t + 128] = d1 * rs * w[t + 128] + b[t + 128];
    o[t + 256] = d2 * rs * w[t + 256] + b[t + 256];
}

// ------------------------- positional embedding ----------------------------
__global__ void posembed_k(const float* __restrict__ bp,
                           const unsigned char* __restrict__ mask)
{
    int row = blockIdx.x;           // NTOK
    int d = threadIdx.x;            // 384
    int b = row >> 10, l = row & 1023;
    int gh = l >> 6, gw = (l >> 3) & 7, gd = l & 7;
    float vr = bp[b * 4 + 2];
    bool m = mask[b] != 0;
    int j = d / 128, r = d - j * 128, f = r & 63;
    float c;
    if (j == 0)      c = (float)gh * (1.f / 15.f);
    else if (j == 1) c = ((float)gw - 4.f) * 0.25f;
    else {
        float v = m ? ((float)gd - 4.f) * vr : (float)gd * vr;
        float den = m ? 4.f * vr : 7.f * vr;
        c = v / den;
    }
    float omega = powf(10000.f, -(float)f * (1.f / 64.f));
    float ph = c * omega;
    g_tok[(size_t)row * D + d] += (r < 64) ? sinf(ph) : cosf(ph);
}

// ------------------------- causal depthwise conv + silu --------------------
__global__ void conv_k(const float* __restrict__ cw, const float* __restrict__ cb)
{
    int row = blockIdx.x;           // NTOK
    int d = threadIdx.x;            // 384
    int l = row & 1023, b = row >> 10;
    float acc = cb[d];
    #pragma unroll
    for (int j = 0; j < 4; j++) {
        int ll = l - 3 + j;
        if (ll >= 0)
            acc = fmaf(g_xz[(size_t)((b << 10) + ll) * (2 * D) + d], cw[d * 4 + j], acc);
    }
    g_xc[(size_t)row * D + d] = acc / (1.f + __expf(-acc));
}

// ------------------------- fused chunked selective scan --------------------
__global__ void scan_k(const float* __restrict__ A_log,
                       const float* __restrict__ dtw,
                       const float* __restrict__ dtb,
                       const float* __restrict__ Dsk)
{
    __shared__ float s_dt[L];
    __shared__ float s_xc[L];
    __shared__ float s_P[NCH][DSTATE];
    __shared__ float s_W[NCH][DSTATE];

    const int tid = threadIdx.x;    // 128
    const int blk = blockIdx.x;     // 0..767
    const int b = blk / D;
    const int d = blk - b * D;

    // ---- phase A: dt + xc stash ----
    float wreg[DTRANK];
    #pragma unroll
    for (int r = 0; r < DTRANK; r++) wreg[r] = __ldg(&dtw[r * D + d]);
    const float bias = __ldg(&dtb[d]);
    const float* dbl_b = g_dbl + (size_t)b * L * DBL_N;
    const float* xc_g  = g_xc + (size_t)b * L * D + d;

    #pragma unroll
    for (int i = 0; i < L / 128; i++) {
        int l = tid + i * 128;
        const float* row = dbl_b + (size_t)l * DBL_N;
        float acc = bias;
        #pragma unroll
        for (int r = 0; r < DTRANK; r++) acc = fmaf(__ldg(row + r), wreg[r], acc);
        s_dt[l] = (acc > 20.f) ? acc : log1pf(__expf(acc));
        s_xc[l] = __ldg(xc_g + (size_t)l * D);
    }
    __syncthreads();

    // ---- phase B: per-chunk local scan ----
    const int u = tid >> 4, lane = tid & 15;
    const float Aa = -__expf(A_log[d * DSTATE + lane]);
    const float* B_g = dbl_b + DTRANK + lane;
    const int l0 = u * CHL;

    float h = 0.f, P = 1.f;
    #pragma unroll 4
    for (int l = 0; l < CHL; l++) {
        float dtv = s_dt[l0 + l];
        float uv  = s_xc[l0 + l];
        float Bv  = __ldg(B_g + (size_t)(l0 + l) * DBL_N);
        float dA  = __expf(dtv * Aa);
        h = fmaf(h, dA, dtv * uv * Bv);
        P *= dA;
    }
    s_P[u][lane] = P;
    s_W[u][lane] = h;
    __syncthreads();

    // ---- phase C: prefix fold ----
    h = 0.f;
    for (int j = 0; j < u; j++)
        h = fmaf(h, s_P[j][lane], s_W[j][lane]);

    // ---- phase D: replay with output ----
    const float Dp = __ldg(&Dsk[d]);
    const float* z_g = g_xz + (size_t)b * L * (2 * D) + D + d;
    float* y_g = g_y + (size_t)b * L * D + d;

    #pragma unroll 4
    for (int l = 0; l < CHL; l++) {
        int ll = l0 + l;
        float dtv = s_dt[ll];
        float uv  = s_xc[ll];
        float Bv  = __ldg(B_g + (size_t)ll * DBL_N);
        float Cv  = __ldg(B_g + (size_t)ll * DBL_N + DSTATE);
        float dA  = __expf(dtv * Aa);
        h = fmaf(h, dA, dtv * uv * Bv);
        float p = h * Cv;
        p += __shfl_xor_sync(0xffffffffu, p, 8);
        p += __shfl_xor_sync(0xffffffffu, p, 4);
        p += __shfl_xor_sync(0xffffffffu, p, 2);
        p += __shfl_xor_sync(0xffffffffu, p, 1);
        if (lane == 0) {
            float zv = __ldg(z_g + (size_t)ll * 2 * D);
            float sz = zv / (1.f + __expf(-zv));
            y_g[(size_t)ll * D] = (p + uv * Dp) * sz;
        }
    }
}

// ------------------------- launch ------------------------------------------
extern "C" void kernel_launch(void* const* d_in, const int* in_sizes, int n_in,
                              void* d_out, int out_size)
{
    const float* x          = (const float*)d_in[0];
    const float* bp         = (const float*)d_in[1];
    const float* patch_w    = (const float*)d_in[2];
    const float* patch_b    = (const float*)d_in[3];
    const float* in_proj_w  = (const float*)d_in[4];
    const float* conv_w     = (const float*)d_in[5];
    const float* conv_b     = (const float*)d_in[6];
    const float* x_proj_w   = (const float*)d_in[7];
    const float* dt_proj_w  = (const float*)d_in[8];
    const float* dt_proj_b  = (const float*)d_in[9];
    const float* A_log      = (const float*)d_in[10];
    const float* Dskip      = (const float*)d_in[11];
    const float* out_proj_w = (const float*)d_in[12];
    const float* norm_w     = (const float*)d_in[13];
    const float* norm_b     = (const float*)d_in[14];
    const float* fw         = (const float*)d_in[15];
    const float* fb         = (const float*)d_in[16];
    const unsigned char* mask = (const unsigned char*)d_in[17];

    float *tok, *h, *xz, *xc, *dbl, *y;
    cudaGetSymbolAddress((void**)&tok, g_tok);
    cudaGetSymbolAddress((void**)&h,   g_h);
    cudaGetSymbolAddress((void**)&xz,  g_xz);
    cudaGetSymbolAddress((void**)&xc,  g_xc);
    cudaGetSymbolAddress((void**)&dbl, g_dbl);
    cudaGetSymbolAddress((void**)&y,   g_y);

    sgemm_patch_k<<<dim3(D / 64, NTOK / 64), 64>>>(x, patch_w, tok, patch_b);
    posembed_k<<<NTOK, D>>>(bp, mask);

    for (int layer = 0; layer < DEPTH; layer++) {
        ln_k<<<NTOK, 128>>>(tok, h, norm_w + layer * D, norm_b + layer * D, dbl);
        sgemm_k<<<dim3((2 * D) / 64, NTOK / 64, 1), 64>>>(h, D,
                in_proj_w + (size_t)layer * D * 2 * D, xz, nullptr, NTOK, 2 * D, D, 0);
        conv_k<<<NTOK, D>>>(conv_w + (size_t)layer * D * 4, conv_b + (size_t)layer * D);
        sgemm_k<<<dim3(1, NTOK / 64, 4), 64>>>(xc, D,
                x_proj_w + (size_t)layer * D * DBL_N, dbl, nullptr, NTOK, DBL_N, D, 0);
        scan_k<<<B_SZ * D, 128>>>(A_log + (size_t)layer * D * DSTATE,
                                  dt_proj_w + (size_t)layer * DTRANK * D,
                                  dt_proj_b + (size_t)layer * D,
                                  Dskip + (size_t)layer * D);
        sgemm_k<<<dim3(D / 64, NTOK / 64, 1), 64>>>(y, D,
                out_proj_w + (size_t)layer * D * D, tok, nullptr, NTOK, D, D, 3);
    }

    ln_k<<<NTOK, 128>>>(tok, (float*)d_out, fw, fb, nullptr);
}

// round 7
// speedup vs baseline: 1.1333x; 1.1333x over previous
#include <cuda_runtime.h>
#include <math.h>
#include <stdint.h>

#define B_SZ 2
#define L 1024
#define D 384
#define PATCH_DIM 4096
#define DEPTH 12
#define DSTATE 16
#define DTRANK 24
#define DBL_N 56
#define NTOK (B_SZ * L)   // 2048
#define NCH 8             // scan chunks
#define CHL (L / NCH)     // 128 steps per chunk

typedef unsigned long long ull;

// ------------------------- scratch (static device) -------------------------
__device__ float g_tok[NTOK * D];
__device__ float g_h[NTOK * D];
__device__ float g_xz[NTOK * 2 * D];
__device__ float g_xc[NTOK * D];
__device__ float g_dbl[NTOK * DBL_N];
__device__ float g_y[NTOK * D];

// ------------------------- f32x2 helpers ------------------------------------
__device__ __forceinline__ ull pack2(float x, float y) {
    ull r; asm("mov.b64 %0, {%1, %2};" : "=l"(r) : "f"(x), "f"(y)); return r;
}
__device__ __forceinline__ void unpack2(ull v, float& x, float& y) {
    asm("mov.b64 {%0, %1}, %2;" : "=f"(x), "=f"(y) : "l"(v));
}
__device__ __forceinline__ void ffma2(ull& d, ull a, ull b) {
    asm("fma.rn.f32x2 %0, %1, %2, %0;" : "+l"(d) : "l"(a), "l"(b));
}

// ------------------------- SIMT GEMM: 128x64x16, 256 threads, 8x4 ----------
// A smem stored k-major (transposed at STS) -> compute reads are LDS.128.
// FFMA2 with m-paired accumulators. Register-staged double buffering.
// epi: 0 none, 1 +bias, 3 C += result. gridDim.z>1 -> split-K atomicAdd.
#define GBM 128
#define GBN 64
#define GBK 16

struct GemmSmem {
    __align__(16) float As[2][GBK][GBM];
    __align__(16) float Bs[2][GBK][GBN];
};

__global__ void sgemm_k(const float* __restrict__ A, int lda,
                        const float* __restrict__ Bm,
                        float* __restrict__ C,
                        const float* __restrict__ bias,
                        int M, int N, int K, int epi)
{
    __shared__ GemmSmem sm;
    const int bm = blockIdx.y * GBM, bn = blockIdx.x * GBN;
    const int t = threadIdx.x;                // 256 threads
    const int tx = t & 15, ty = t >> 4;       // 16x16 thread grid, 8x4 per thread

    const int ksplit = gridDim.z;
    const int kc = K / ksplit;                // multiple of GBK by caller
    const int kstart = blockIdx.z * kc;
    const int niters = kc / GBK;

    // A loader: row = t&127, k-offset = (t>>7)*8 (2 float4 each)
    const int ar = t & 127, akq = (t >> 7) << 3;
    const float* Arow = A + (size_t)(bm + ar) * lda + kstart + akq;
    // B loader: row = t>>4 (0..15), col = (t&15)*4 (1 float4 each)
    const int br = t >> 4, bc = (t & 15) << 2;
    const bool b_ok = (bn + bc) < N;

    float4 aR0, aR1, bR;
    auto ldA = [&](int it) {
        const float* p = Arow + it * GBK;
        aR0 = *reinterpret_cast<const float4*>(p);
        aR1 = *reinterpret_cast<const float4*>(p + 4);
    };
    auto ldB = [&](int it) {
        if (b_ok) {
            const float* p = Bm + (size_t)(kstart + it * GBK + br) * N + bn + bc;
            bR = *reinterpret_cast<const float4*>(p);
        } else {
            bR = make_float4(0.f, 0.f, 0.f, 0.f);
        }
    };
    auto stAB = [&](int buf) {
        sm.As[buf][akq + 0][ar] = aR0.x;
        sm.As[buf][akq + 1][ar] = aR0.y;
        sm.As[buf][akq + 2][ar] = aR0.z;
        sm.As[buf][akq + 3][ar] = aR0.w;
        sm.As[buf][akq + 4][ar] = aR1.x;
        sm.As[buf][akq + 5][ar] = aR1.y;
        sm.As[buf][akq + 6][ar] = aR1.z;
        sm.As[buf][akq + 7][ar] = aR1.w;
        *reinterpret_cast<float4*>(&sm.Bs[buf][br][bc]) = bR;
    };

    ull acc[4][4];
    #pragma unroll
    for (int i = 0; i < 4; i++)
        #pragma unroll
        for (int j = 0; j < 4; j++) acc[i][j] = 0ull;

    ldA(0); ldB(0); stAB(0);
    __syncthreads();

    for (int it = 0; it < niters; it++) {
        const int buf = it & 1;
        if (it + 1 < niters) { ldA(it + 1); ldB(it + 1); }
        #pragma unroll
        for (int kk = 0; kk < GBK; kk++) {
            float4 af0 = *reinterpret_cast<const float4*>(&sm.As[buf][kk][ty * 8]);
            float4 af1 = *reinterpret_cast<const float4*>(&sm.As[buf][kk][ty * 8 + 4]);
            float4 bf  = *reinterpret_cast<const float4*>(&sm.Bs[buf][kk][tx * 4]);
            ull ap[4];
            ap[0] = pack2(af0.x, af0.y); ap[1] = pack2(af0.z, af0.w);
            ap[2] = pack2(af1.x, af1.y); ap[3] = pack2(af1.z, af1.w);
            ull bd[4];
            bd[0] = pack2(bf.x, bf.x); bd[1] = pack2(bf.y, bf.y);
            bd[2] = pack2(bf.z, bf.z); bd[3] = pack2(bf.w, bf.w);
            #pragma unroll
            for (int i = 0; i < 4; i++)
                #pragma unroll
                for (int j = 0; j < 4; j++)
                    ffma2(acc[i][j], ap[i], bd[j]);
        }
        __syncthreads();
        if (it + 1 < niters) { stAB(buf ^ 1); __syncthreads(); }
    }

    // epilogue: acc[i][j] -> rows bm+ty*8+2i, +2i+1; col bn+tx*4+j
    const int n0 = bn + tx * 4;
    if (ksplit > 1) {
        #pragma unroll
        for (int i = 0; i < 4; i++) {
            int r0 = bm + ty * 8 + 2 * i;
            #pragma unroll
            for (int j = 0; j < 4; j++) {
                int col = n0 + j;
                if (col < N) {
                    float v0, v1; unpack2(acc[i][j], v0, v1);
                    atomicAdd(&C[(size_t)r0 * N + col], v0);
                    atomicAdd(&C[(size_t)(r0 + 1) * N + col], v1);
                }
            }
        }
    } else {
        #pragma unroll
        for (int i = 0; i < 4; i++) {
            float lo[4], hi[4];
            #pragma unroll
            for (int j = 0; j < 4; j++) unpack2(acc[i][j], lo[j], hi[j]);
            int r0 = bm + ty * 8 + 2 * i;
            float* C0 = C + (size_t)r0 * N + n0;
            float* C1 = C + (size_t)(r0 + 1) * N + n0;
            if (epi == 1) {
                #pragma unroll
                for (int j = 0; j < 4; j++) {
                    float bv = bias[n0 + j];
                    lo[j] += bv; hi[j] += bv;
                }
            } else if (epi == 3) {
                float4 c0 = *reinterpret_cast<float4*>(C0);
                float4 c1 = *reinterpret_cast<float4*>(C1);
                lo[0] += c0.x; lo[1] += c0.y; lo[2] += c0.z; lo[3] += c0.w;
                hi[0] += c1.x; hi[1] += c1.y; hi[2] += c1.z; hi[3] += c1.w;
            }
            *reinterpret_cast<float4*>(C0) = make_float4(lo[0], lo[1], lo[2], lo[3]);
            *reinterpret_cast<float4*>(C1) = make_float4(hi[0], hi[1], hi[2], hi[3]);
        }
    }
}

// ------------------------- patchify GEMM (im2col fused) --------------------
__global__ void sgemm_patch_k(const float* __restrict__ X,
                              const float* __restrict__ Bm,
                              float* __restrict__ C,
                              const float* __restrict__ bias)
{
    __shared__ GemmSmem sm;
    const int bm = blockIdx.y * GBM, bn = blockIdx.x * GBN;
    const int t = threadIdx.x;
    const int tx = t & 15, ty = t >> 4;
    const int N = D;
    const int niters = PATCH_DIM / GBK;

    const int ar = t & 127, akq = (t >> 7) << 3;
    const int m = bm + ar;
    const int b = m >> 10, l = m & 1023;
    const int gh = l >> 6, gw = (l >> 3) & 7, gd = l & 7;
    const size_t xbase = ((size_t)(b * 256 + gh * 16) * 256 + gw * 32) * 64 + gd * 8;

    const int br = t >> 4, bc = (t & 15) << 2;

    float4 aR0, aR1, bR;
    auto ldA = [&](int it) {
        int k = it * GBK + akq;
        int ph = k >> 8, pw = (k >> 3) & 31, pd = k & 7;
        aR0 = *reinterpret_cast<const float4*>(X + xbase + (size_t)ph * 16384 + pw * 64 + pd);
        int k2 = k + 4;
        ph = k2 >> 8; pw = (k2 >> 3) & 31; pd = k2 & 7;
        aR1 = *reinterpret_cast<const float4*>(X + xbase + (size_t)ph * 16384 + pw * 64 + pd);
    };
    auto ldB = [&](int it) {
        const float* p = Bm + (size_t)(it * GBK + br) * N + bn + bc;
        bR = *reinterpret_cast<const float4*>(p);
    };
    auto stAB = [&](int buf) {
        sm.As[buf][akq + 0][ar] = aR0.x;
        sm.As[buf][akq + 1][ar] = aR0.y;
        sm.As[buf][akq + 2][ar] = aR0.z;
        sm.As[buf][akq + 3][ar] = aR0.w;
        sm.As[buf][akq + 4][ar] = aR1.x;
        sm.As[buf][akq + 5][ar] = aR1.y;
        sm.As[buf][akq + 6][ar] = aR1.z;
        sm.As[buf][akq + 7][ar] = aR1.w;
        *reinterpret_cast<float4*>(&sm.Bs[buf][br][bc]) = bR;
    };

    ull acc[4][4];
    #pragma unroll
    for (int i = 0; i < 4; i++)
        #pragma unroll
        for (int j = 0; j < 4; j++) acc[i][j] = 0ull;

    ldA(0); ldB(0); stAB(0);
    __syncthreads();

    for (int it = 0; it < niters; it++) {
        const int buf = it & 1;
        if (it + 1 < niters) { ldA(it + 1); ldB(it + 1); }
        #pragma unroll
        for (int kk = 0; kk < GBK; kk++) {
            float4 af0 = *reinterpret_cast<const float4*>(&sm.As[buf][kk][ty * 8]);
            float4 af1 = *reinterpret_cast<const float4*>(&sm.As[buf][kk][ty * 8 + 4]);
            float4 bf  = *reinterpret_cast<const float4*>(&sm.Bs[buf][kk][tx * 4]);
            ull ap[4];
            ap[0] = pack2(af0.x, af0.y); ap[1] = pack2(af0.z, af0.w);
            ap[2] = pack2(af1.x, af1.y); ap[3] = pack2(af1.z, af1.w);
            ull bd[4];
            bd[0] = pack2(bf.x, bf.x); bd[1] = pack2(bf.y, bf.y);
            bd[2] = pack2(bf.z, bf.z); bd[3] = pack2(bf.w, bf.w);
            #pragma unroll
            for (int i = 0; i < 4; i++)
                #pragma unroll
                for (int j = 0; j < 4; j++)
                    ffma2(acc[i][j], ap[i], bd[j]);
        }
        __syncthreads();
        if (it + 1 < niters) { stAB(buf ^ 1); __syncthreads(); }
    }

    const int n0 = bn + tx * 4;
    #pragma unroll
    for (int i = 0; i < 4; i++) {
        float lo[4], hi[4];
        #pragma unroll
        for (int j = 0; j < 4; j++) {
            unpack2(acc[i][j], lo[j], hi[j]);
            float bv = bias[n0 + j];
            lo[j] += bv; hi[j] += bv;
        }
        int r0 = bm + ty * 8 + 2 * i;
        float* C0 = C + (size_t)r0 * N + n0;
        float* C1 = C + (size_t)(r0 + 1) * N + n0;
        *reinterpret_cast<float4*>(C0) = make_float4(lo[0], lo[1], lo[2], lo[3]);
        *reinterpret_cast<float4*>(C1) = make_float4(hi[0], hi[1], hi[2], hi[3]);
    }
}

// ------------------------- LayerNorm (row of 384) + dbl zeroing ------------
__global__ void ln_k(const float* __restrict__ in, float* __restrict__ out,
                     const float* __restrict__ w, const float* __restrict__ b,
                     float* __restrict__ zbuf)
{
    int row = blockIdx.x;
    int t = threadIdx.x;   // 128 threads
    if (zbuf != nullptr && t < DBL_N) zbuf[(size_t)row * DBL_N + t] = 0.f;
    const float* r = in + (size_t)row * D;
    float v0 = r[t], v1 = r[t + 128], v2 = r[t + 256];
    float s = v0 + v1 + v2;
    __shared__ float sh[4], sh2[4];
    #pragma unroll
    for (int o = 16; o; o >>= 1) s += __shfl_xor_sync(~0u, s, o);
    if ((t & 31) == 0) sh[t >> 5] = s;
    __syncthreads();
    float mu = (sh[0] + sh[1] + sh[2] + sh[3]) * (1.f / 384.f);
    float d0 = v0 - mu, d1 = v1 - mu, d2 = v2 - mu;
    float q = d0 * d0 + d1 * d1 + d2 * d2;
    #pragma unroll
    for (int o = 16; o; o >>= 1) q += __shfl_xor_sync(~0u, q, o);
    if ((t & 31) == 0) sh2[t >> 5] = q;
    __syncthreads();
    float var = (sh2[0] + sh2[1] + sh2[2] + sh2[3]) * (1.f / 384.f);
    float rs = rsqrtf(var + 1e-5f);
    float* o = out + (size_t)row * D;
    o[t]       = d0 * rs * w[t]       + b[t];
    o[t + 128] = d1 * rs * w[t + 128] + b[t + 128];
    o[t + 256] = d2 * rs * w[t + 256] + b[t + 256];
}

// ------------------------- positional embedding ----------------------------
__global__ void posembed_k(const float* __restrict__ bp,
                           const unsigned char* __restrict__ mask)
{
    int row = blockIdx.x;           // NTOK
    int d = threadIdx.x;            // 384
    int b = row >> 10, l = row & 1023;
    int gh = l >> 6, gw = (l >> 3) & 7, gd = l & 7;
    float vr = bp[b * 4 + 2];
    bool m = mask[b] != 0;
    int j = d / 128, r = d - j * 128, f = r & 63;
    float c;
    if (j == 0)      c = (float)gh * (1.f / 15.f);
    else if (j == 1) c = ((float)gw - 4.f) * 0.25f;
    else {
        float v = m ? ((float)gd - 4.f) * vr : (float)gd * vr;
        float den = m ? 4.f * vr : 7.f * vr;
        c = v / den;
    }
    float omega = powf(10000.f, -(float)f * (1.f / 64.f));
    float ph = c * omega;
    g_tok[(size_t)row * D + d] += (r < 64) ? sinf(ph) : cosf(ph);
}

// ------------------------- causal depthwise conv + silu --------------------
__global__ void conv_k(const float* __restrict__ cw, const float* __restrict__ cb)
{
    int row = blockIdx.x;           // NTOK
    int d = threadIdx.x;            // 384
    int l = row & 1023, b = row >> 10;
    float acc = cb[d];
    #pragma unroll
    for (int j = 0; j < 4; j++) {
        int ll = l - 3 + j;
        if (ll >= 0)
            acc = fmaf(g_xz[(size_t)((b << 10) + ll) * (2 * D) + d], cw[d * 4 + j], acc);
    }
    g_xc[(size_t)row * D + d] = acc / (1.f + __expf(-acc));
}

// ------------------------- fused chunked selective scan --------------------
__global__ void scan_k(const float* __restrict__ A_log,
                       const float* __restrict__ dtw,
                       const float* __restrict__ dtb,
                       const float* __restrict__ Dsk)
{
    __shared__ float s_dt[L];
    __shared__ float s_xc[L];
    __shared__ float s_P[NCH][DSTATE];
    __shared__ float s_W[NCH][DSTATE];

    const int tid = threadIdx.x;    // 128
    const int blk = blockIdx.x;     // 0..767
    const int b = blk / D;
    const int d = blk - b * D;

    // ---- phase A: dt + xc stash ----
    float wreg[DTRANK];
    #pragma unroll
    for (int r = 0; r < DTRANK; r++) wreg[r] = __ldg(&dtw[r * D + d]);
    const float bias = __ldg(&dtb[d]);
    const float* dbl_b = g_dbl + (size_t)b * L * DBL_N;
    const float* xc_g  = g_xc + (size_t)b * L * D + d;

    #pragma unroll
    for (int i = 0; i < L / 128; i++) {
        int l = tid + i * 128;
        const float* row = dbl_b + (size_t)l * DBL_N;
        float acc = bias;
        #pragma unroll
        for (int r = 0; r < DTRANK; r++) acc = fmaf(__ldg(row + r), wreg[r], acc);
        s_dt[l] = (acc > 20.f) ? acc : log1pf(__expf(acc));
        s_xc[l] = __ldg(xc_g + (size_t)l * D);
    }
    __syncthreads();

    // ---- phase B: per-chunk local scan ----
    const int u = tid >> 4, lane = tid & 15;
    const float Aa = -__expf(A_log[d * DSTATE + lane]);
    const float* B_g = dbl_b + DTRANK + lane;
    const int l0 = u * CHL;

    float h = 0.f, P = 1.f;
    #pragma unroll 4
    for (int l = 0; l < CHL; l++) {
        float dtv = s_dt[l0 + l];
        float uv  = s_xc[l0 + l];
        float Bv  = __ldg(B_g + (size_t)(l0 + l) * DBL_N);
        float dA  = __expf(dtv * Aa);
        h = fmaf(h, dA, dtv * uv * Bv);
        P *= dA;
    }
    s_P[u][lane] = P;
    s_W[u][lane] = h;
    __syncthreads();

    // ---- phase C: prefix fold ----
    h = 0.f;
    for (int j = 0; j < u; j++)
        h = fmaf(h, s_P[j][lane], s_W[j][lane]);

    // ---- phase D: replay with output ----
    const float Dp = __ldg(&Dsk[d]);
    const float* z_g = g_xz + (size_t)b * L * (2 * D) + D + d;
    float* y_g = g_y + (size_t)b * L * D + d;

    #pragma unroll 4
    for (int l = 0; l < CHL; l++) {
        int ll = l0 + l;
        float dtv = s_dt[ll];
        float uv  = s_xc[ll];
        float Bv  = __ldg(B_g + (size_t)ll * DBL_N);
        float Cv  = __ldg(B_g + (size_t)ll * DBL_N + DSTATE);
        float dA  = __expf(dtv * Aa);
        h = fmaf(h, dA, dtv * uv * Bv);
        float p = h * Cv;
        p += __shfl_xor_sync(0xffffffffu, p, 8);
        p += __shfl_xor_sync(0xffffffffu, p, 4);
        p += __shfl_xor_sync(0xffffffffu, p, 2);
        p += __shfl_xor_sync(0xffffffffu, p, 1);
        if (lane == 0) {
            float zv = __ldg(z_g + (size_t)ll * 2 * D);
            float sz = zv / (1.f + __expf(-zv));
            y_g[(size_t)ll * D] = (p + uv * Dp) * sz;
        }
    }
}

// ------------------------- launch ------------------------------------------
extern "C" void kernel_launch(void* const* d_in, const int* in_sizes, int n_in,
                              void* d_out, int out_size)
{
    const float* x          = (const float*)d_in[0];
    const float* bp         = (const float*)d_in[1];
    const float* patch_w    = (const float*)d_in[2];
    const float* patch_b    = (const float*)d_in[3];
    const float* in_proj_w  = (const float*)d_in[4];
    const float* conv_w     = (const float*)d_in[5];
    const float* conv_b     = (const float*)d_in[6];
    const float* x_proj_w   = (const float*)d_in[7];
    const float* dt_proj_w  = (const float*)d_in[8];
    const float* dt_proj_b  = (const float*)d_in[9];
    const float* A_log      = (const float*)d_in[10];
    const float* Dskip      = (const float*)d_in[11];
    const float* out_proj_w = (const float*)d_in[12];
    const float* norm_w     = (const float*)d_in[13];
    const float* norm_b     = (const float*)d_in[14];
    const float* fw         = (const float*)d_in[15];
    const float* fb         = (const float*)d_in[16];
    const unsigned char* mask = (const unsigned char*)d_in[17];

    float *tok, *h, *xz, *xc, *dbl, *y;
    cudaGetSymbolAddress((void**)&tok, g_tok);
    cudaGetSymbolAddress((void**)&h,   g_h);
    cudaGetSymbolAddress((void**)&xz,  g_xz);
    cudaGetSymbolAddress((void**)&xc,  g_xc);
    cudaGetSymbolAddress((void**)&dbl, g_dbl);
    cudaGetSymbolAddress((void**)&y,   g_y);

    sgemm_patch_k<<<dim3(D / GBN, NTOK / GBM), 256>>>(x, patch_w, tok, patch_b);
    posembed_k<<<NTOK, D>>>(bp, mask);

    for (int layer = 0; layer < DEPTH; layer++) {
        ln_k<<<NTOK, 128>>>(tok, h, norm_w + layer * D, norm_b + layer * D, dbl);
        sgemm_k<<<dim3((2 * D) / GBN, NTOK / GBM, 1), 256>>>(h, D,
                in_proj_w + (size_t)layer * D * 2 * D, xz, nullptr, NTOK, 2 * D, D, 0);
        conv_k<<<NTOK, D>>>(conv_w + (size_t)layer * D * 4, conv_b + (size_t)layer * D);
        sgemm_k<<<dim3(1, NTOK / GBM, 4), 256>>>(xc, D,
                x_proj_w + (size_t)layer * D * DBL_N, dbl, nullptr, NTOK, DBL_N, D, 0);
        scan_k<<<B_SZ * D, 128>>>(A_log + (size_t)layer * D * DSTATE,
                                  dt_proj_w + (size_t)layer * DTRANK * D,
                                  dt_proj_b + (size_t)layer * D,
                                  Dskip + (size_t)layer * D);
        sgemm_k<<<dim3(D / GBN, NTOK / GBM, 1), 256>>>(y, D,
                out_proj_w + (size_t)layer * D * D, tok, nullptr, NTOK, D, D, 3);
    }

    ln_k<<<NTOK, 128>>>(tok, (float*)d_out, fw, fb, nullptr);
}

// round 8
// speedup vs baseline: 1.2373x; 1.0918x over previous
#include <cuda_runtime.h>
#include <math.h>
#include <stdint.h>

#define B_SZ 2
#define L 1024
#define D 384
#define PATCH_DIM 4096
#define DEPTH 12
#define DSTATE 16
#define DTRANK 24
#define DBL_N 56
#define NTOK (B_SZ * L)   // 2048
#define NCH 8             // scan chunks
#define CHL (L / NCH)     // 128 steps per chunk

typedef unsigned long long ull;

// ------------------------- scratch (static device) -------------------------
__device__ float g_tok[NTOK * D];
__device__ float g_h[NTOK * D];
__device__ float g_xz[NTOK * 2 * D];
__device__ float g_xc[NTOK * D];
__device__ float g_dbl[NTOK * DBL_N];
__device__ float g_y[NTOK * D];

// ------------------------- cp.async + f32x2 helpers ------------------------
__device__ __forceinline__ void cp_async16(uint32_t dst, const void* src, bool pred) {
    int sz = pred ? 16 : 0;
    asm volatile("cp.async.ca.shared.global [%0], [%1], 16, %2;\n"
                 :: "r"(dst), "l"(src), "r"(sz));
}
__device__ __forceinline__ void cp_commit() {
    asm volatile("cp.async.commit_group;\n");
}
template <int N>
__device__ __forceinline__ void cp_wait() {
    asm volatile("cp.async.wait_group %0;\n" :: "n"(N));
}
__device__ __forceinline__ ull pack2(float x, float y) {
    ull r; asm("mov.b64 %0, {%1, %2};" : "=l"(r) : "f"(x), "f"(y)); return r;
}
__device__ __forceinline__ void unpack2(ull v, float& x, float& y) {
    asm("mov.b64 {%0, %1}, %2;" : "=f"(x), "=f"(y) : "l"(v));
}
__device__ __forceinline__ void ffma2(ull& d, ull a, ull b) {
    asm("fma.rn.f32x2 %0, %1, %2, %0;" : "+l"(d) : "l"(a), "l"(b));
}

// ------------------------- pipelined SGEMM 64x64 (vector LDS + FFMA2) ------
#define BM 64
#define BN 64
#define BK 16
#define ASTRIDE 20   // 80 B row stride: 16B-aligned, odd 16B phase -> no conflicts

struct SmemGemm {
    __align__(16) float As[2][BM * ASTRIDE];
    __align__(16) float Bs[2][BK * BN];
};

// inner microkernel: kk blocked by 4, A read as LDS.128 along k
__device__ __forceinline__ void gemm_inner(const float* __restrict__ As,
                                           const float* __restrict__ Bsr,
                                           int m0, int n0, ull acc2[4][2])
{
    #pragma unroll
    for (int k4 = 0; k4 < BK; k4 += 4) {
        float4 a[4];
        #pragma unroll
        for (int i = 0; i < 4; i++)
            a[i] = *reinterpret_cast<const float4*>(&As[(m0 + i) * ASTRIDE + k4]);
        #pragma unroll
        for (int q = 0; q < 4; q++) {
            float4 bq = *reinterpret_cast<const float4*>(&Bsr[(k4 + q) * BN + n0]);
            ull b01 = pack2(bq.x, bq.y);
            ull b23 = pack2(bq.z, bq.w);
            #pragma unroll
            for (int i = 0; i < 4; i++) {
                const float* af = &a[i].x;
                ull ap = pack2(af[q], af[q]);
                ffma2(acc2[i][0], ap, b01);
                ffma2(acc2[i][1], ap, b23);
            }
        }
    }
}

// epi: 0 none, 1 +bias, 3 C += result. gridDim.z>1 -> split-K atomicAdd.
__global__ void sgemm_k(const float* __restrict__ A, int lda,
                        const float* __restrict__ Bm,
                        float* __restrict__ C,
                        const float* __restrict__ bias,
                        int M, int N, int K, int epi)
{
    __shared__ SmemGemm sm;
    const int bm = blockIdx.y * BM, bn = blockIdx.x * BN;
    const int tid = threadIdx.x;

    const int ksplit = gridDim.z;
    const int kc = K / ksplit;
    const int kstart = blockIdx.z * kc;
    const int kend = kstart + kc;
    const int niters = (kc + BK - 1) / BK;

    const int am  = tid >> 2;
    const int akq = (tid & 3) << 2;
    const int bkb = tid >> 4;
    const int bn4 = (tid & 15) << 2;
    const bool bn_ok = (bn + bn4) < N;

    const float* Arow = A + (size_t)(bm + am) * lda;

    uint32_t sAs = (uint32_t)__cvta_generic_to_shared(&sm.As[0][0]);
    uint32_t sBs = (uint32_t)__cvta_generic_to_shared(&sm.Bs[0][0]);

    auto load_stage = [&](int it, int buf) {
        int k0 = kstart + it * BK;
        {
            int k = k0 + akq;
            bool p = k < kend;
            const float* src = p ? (Arow + k) : A;
            cp_async16(sAs + (buf * BM * ASTRIDE + am * ASTRIDE + akq) * 4, src, p);
        }
        {
            int k = k0 + bkb;
            bool p = (k < kend) && bn_ok;
            const float* src = p ? (Bm + (size_t)k * N + bn + bn4) : Bm;
            cp_async16(sBs + (buf * BK * BN + bkb * BN + bn4) * 4, src, p);
        }
    };

    const int ty = tid >> 4, tx = tid & 15;
    const int m0 = ty * 4, n0 = tx * 4;

    ull acc2[4][2];
    #pragma unroll
    for (int i = 0; i < 4; i++) { acc2[i][0] = 0ull; acc2[i][1] = 0ull; }

    load_stage(0, 0); cp_commit();
    if (niters > 1) load_stage(1, 1);
    cp_commit();

    for (int it = 0; it < niters; it++) {
        cp_wait<1>();
        __syncthreads();
        const int buf = it & 1;
        gemm_inner(&sm.As[buf][0], &sm.Bs[buf][0], m0, n0, acc2);
        __syncthreads();
        if (it + 2 < niters) load_stage(it + 2, buf);
        cp_commit();
    }

    #pragma unroll
    for (int i = 0; i < 4; i++) {
        int row = bm + m0 + i;
        float v[4];
        unpack2(acc2[i][0], v[0], v[1]);
        unpack2(acc2[i][1], v[2], v[3]);
        #pragma unroll
        for (int j = 0; j < 4; j++) {
            int col = bn + n0 + j;
            if (col < N) {
                size_t off = (size_t)row * N + col;
                float vv = v[j];
                if (ksplit > 1) {
                    atomicAdd(&C[off], vv);
                } else {
                    if (epi == 1) vv += bias[col];
                    if (epi == 3) vv += C[off];
                    C[off] = vv;
                }
            }
        }
    }
}

// ------------------------- patchify GEMM (im2col fused) --------------------
__global__ void sgemm_patch_k(const float* __restrict__ X,
                              const float* __restrict__ Bm,
                              float* __restrict__ C,
                              const float* __restrict__ bias)
{
    __shared__ SmemGemm sm;
    const int bm = blockIdx.y * BM, bn = blockIdx.x * BN;
    const int tid = threadIdx.x;
    const int N = D, K = PATCH_DIM;
    const int niters = K / BK;

    const int am  = tid >> 2;
    const int akq = (tid & 3) << 2;
    const int bkb = tid >> 4;
    const int bn4 = (tid & 15) << 2;

    const int m = bm + am;
    const int b = m >> 10, l = m & 1023;
    const int gh = l >> 6, gw = (l >> 3) & 7, gd = l & 7;
    const size_t xbase = ((size_t)(b * 256 + gh * 16) * 256 + gw * 32) * 64 + gd * 8;

    uint32_t sAs = (uint32_t)__cvta_generic_to_shared(&sm.As[0][0]);
    uint32_t sBs = (uint32_t)__cvta_generic_to_shared(&sm.Bs[0][0]);

    auto load_stage = [&](int it, int buf) {
        int k0 = it * BK;
        {
            int k = k0 + akq;
            int ph = k >> 8, pw = (k >> 3) & 31, pd = k & 7;
            const float* src = X + xbase + (size_t)ph * 16384 + pw * 64 + pd;
            cp_async16(sAs + (buf * BM * ASTRIDE + am * ASTRIDE + akq) * 4, src, true);
        }
        {
            int k = k0 + bkb;
            const float* src = Bm + (size_t)k * N + bn + bn4;
            cp_async16(sBs + (buf * BK * BN + bkb * BN + bn4) * 4, src, true);
        }
    };

    const int ty = tid >> 4, tx = tid & 15;
    const int m0 = ty * 4, n0 = tx * 4;

    ull acc2[4][2];
    #pragma unroll
    for (int i = 0; i < 4; i++) { acc2[i][0] = 0ull; acc2[i][1] = 0ull; }

    load_stage(0, 0); cp_commit();
    load_stage(1, 1); cp_commit();

    for (int it = 0; it < niters; it++) {
        cp_wait<1>();
        __syncthreads();
        const int buf = it & 1;
        gemm_inner(&sm.As[buf][0], &sm.Bs[buf][0], m0, n0, acc2);
        __syncthreads();
        if (it + 2 < niters) load_stage(it + 2, buf);
        cp_commit();
    }

    #pragma unroll
    for (int i = 0; i < 4; i++) {
        int row = bm + m0 + i;
        float v[4];
        unpack2(acc2[i][0], v[0], v[1]);
        unpack2(acc2[i][1], v[2], v[3]);
        #pragma unroll
        for (int j = 0; j < 4; j++) {
            int col = bn + n0 + j;
            C[(size_t)row * N + col] = v[j] + bias[col];
        }
    }
}

// ------------------------- LayerNorm (row of 384) + dbl zeroing ------------
__global__ void ln_k(const float* __restrict__ in, float* __restrict__ out,
                     const float* __restrict__ w, const float* __restrict__ b,
                     float* __restrict__ zbuf)
{
    int row = blockIdx.x;
    int t = threadIdx.x;   // 128 threads
    if (zbuf != nullptr && t < DBL_N) zbuf[(size_t)row * DBL_N + t] = 0.f;
    const float* r = in + (size_t)row * D;
    float v0 = r[t], v1 = r[t + 128], v2 = r[t + 256];
    float s = v0 + v1 + v2;
    __shared__ float sh[4], sh2[4];
    #pragma unroll
    for (int o = 16; o; o >>= 1) s += __shfl_xor_sync(~0u, s, o);
    if ((t & 31) == 0) sh[t >> 5] = s;
    __syncthreads();
    float mu = (sh[0] + sh[1] + sh[2] + sh[3]) * (1.f / 384.f);
    float d0 = v0 - mu, d1 = v1 - mu, d2 = v2 - mu;
    float q = d0 * d0 + d1 * d1 + d2 * d2;
    #pragma unroll
    for (int o = 16; o; o >>= 1) q += __shfl_xor_sync(~0u, q, o);
    if ((t & 31) == 0) sh2[t >> 5] = q;
    __syncthreads();
    float var = (sh2[0] + sh2[1] + sh2[2] + sh2[3]) * (1.f / 384.f);
    float rs = rsqrtf(var + 1e-5f);
    float* o = out + (size_t)row * D;
    o[t]       = d0 * rs * w[t]       + b[t];
    o[t + 128] = d1 * rs * w[t + 128] + b[t + 128];
    o[t + 256] = d2 * rs * w[t + 256] + b[t + 256];
}

// ------------------------- positional embedding ----------------------------
__global__ void posembed_k(const float* __restrict__ bp,
                           const unsigned char* __restrict__ mask)
{
    int row = blockIdx.x;           // NTOK
    int d = threadIdx.x;            // 384
    int b = row >> 10, l = row & 1023;
    int gh = l >> 6, gw = (l >> 3) & 7, gd = l & 7;
    float vr = bp[b * 4 + 2];
    bool m = mask[b] != 0;
    int j = d / 128, r = d - j * 128, f = r & 63;
    float c;
    if (j == 0)      c = (float)gh * (1.f / 15.f);
    else if (j == 1) c = ((float)gw - 4.f) * 0.25f;
    else {
        float v = m ? ((float)gd - 4.f) * vr : (float)gd * vr;
        float den = m ? 4.f * vr : 7.f * vr;
        c = v / den;
    }
    float omega = powf(10000.f, -(float)f * (1.f / 64.f));
    float ph = c * omega;
    g_tok[(size_t)row * D + d] += (r < 64) ? sinf(ph) : cosf(ph);
}

// ------------------------- causal depthwise conv + silu --------------------
__global__ void conv_k(const float* __restrict__ cw, const float* __restrict__ cb)
{
    int row = blockIdx.x;           // NTOK
    int d = threadIdx.x;            // 384
    int l = row & 1023, b = row >> 10;
    float acc = cb[d];
    #pragma unroll
    for (int j = 0; j < 4; j++) {
        int ll = l - 3 + j;
        if (ll >= 0)
            acc = fmaf(g_xz[(size_t)((b << 10) + ll) * (2 * D) + d], cw[d * 4 + j], acc);
    }
    g_xc[(size_t)row * D + d] = acc / (1.f + __expf(-acc));
}

// ------------------------- fused chunked selective scan --------------------
__global__ void scan_k(const float* __restrict__ A_log,
                       const float* __restrict__ dtw,
                       const float* __restrict__ dtb,
                       const float* __restrict__ Dsk)
{
    __shared__ float s_dt[L];
    __shared__ float s_xc[L];
    __shared__ float s_P[NCH][DSTATE];
    __shared__ float s_W[NCH][DSTATE];

    const int tid = threadIdx.x;    // 128
    const int blk = blockIdx.x;     // 0..767
    const int b = blk / D;
    const int d = blk - b * D;

    // ---- phase A: dt + xc stash ----
    float wreg[DTRANK];
    #pragma unroll
    for (int r = 0; r < DTRANK; r++) wreg[r] = __ldg(&dtw[r * D + d]);
    const float bias = __ldg(&dtb[d]);
    const float* dbl_b = g_dbl + (size_t)b * L * DBL_N;
    const float* xc_g  = g_xc + (size_t)b * L * D + d;

    #pragma unroll
    for (int i = 0; i < L / 128; i++) {
        int l = tid + i * 128;
        const float* row = dbl_b + (size_t)l * DBL_N;
        float acc = bias;
        #pragma unroll
        for (int r = 0; r < DTRANK; r++) acc = fmaf(__ldg(row + r), wreg[r], acc);
        s_dt[l] = (acc > 20.f) ? acc : log1pf(__expf(acc));
        s_xc[l] = __ldg(xc_g + (size_t)l * D);
    }
    __syncthreads();

    // ---- phase B: per-chunk local scan ----
    const int u = tid >> 4, lane = tid & 15;
    const float Aa = -__expf(A_log[d * DSTATE + lane]);
    const float* B_g = dbl_b + DTRANK + lane;
    const int l0 = u * CHL;

    float h = 0.f, P = 1.f;
    #pragma unroll 4
    for (int l = 0; l < CHL; l++) {
        float dtv = s_dt[l0 + l];
        float uv  = s_xc[l0 + l];
        float Bv  = __ldg(B_g + (size_t)(l0 + l) * DBL_N);
        float dA  = __expf(dtv * Aa);
        h = fmaf(h, dA, dtv * uv * Bv);
        P *= dA;
    }
    s_P[u][lane] = P;
    s_W[u][lane] = h;
    __syncthreads();

    // ---- phase C: prefix fold ----
    h = 0.f;
    for (int j = 0; j < u; j++)
        h = fmaf(h, s_P[j][lane], s_W[j][lane]);

    // ---- phase D: replay with output ----
    const float Dp = __ldg(&Dsk[d]);
    const float* z_g = g_xz + (size_t)b * L * (2 * D) + D + d;
    float* y_g = g_y + (size_t)b * L * D + d;

    #pragma unroll 4
    for (int l = 0; l < CHL; l++) {
        int ll = l0 + l;
        float dtv = s_dt[ll];
        float uv  = s_xc[ll];
        float Bv  = __ldg(B_g + (size_t)ll * DBL_N);
        float Cv  = __ldg(B_g + (size_t)ll * DBL_N + DSTATE);
        float dA  = __expf(dtv * Aa);
        h = fmaf(h, dA, dtv * uv * Bv);
        float p = h * Cv;
        p += __shfl_xor_sync(0xffffffffu, p, 8);
        p += __shfl_xor_sync(0xffffffffu, p, 4);
        p += __shfl_xor_sync(0xffffffffu, p, 2);
        p += __shfl_xor_sync(0xffffffffu, p, 1);
        if (lane == 0) {
            float zv = __ldg(z_g + (size_t)ll * 2 * D);
            float sz = zv / (1.f + __expf(-zv));
            y_g[(size_t)ll * D] = (p + uv * Dp) * sz;
        }
    }
}

// ------------------------- launch ------------------------------------------
extern "C" void kernel_launch(void* const* d_in, const int* in_sizes, int n_in,
                              void* d_out, int out_size)
{
    const float* x          = (const float*)d_in[0];
    const float* bp         = (const float*)d_in[1];
    const float* patch_w    = (const float*)d_in[2];
    const float* patch_b    = (const float*)d_in[3];
    const float* in_proj_w  = (const float*)d_in[4];
    const float* conv_w     = (const float*)d_in[5];
    const float* conv_b     = (const float*)d_in[6];
    const float* x_proj_w   = (const float*)d_in[7];
    const float* dt_proj_w  = (const float*)d_in[8];
    const float* dt_proj_b  = (const float*)d_in[9];
    const float* A_log      = (const float*)d_in[10];
    const float* Dskip      = (const float*)d_in[11];
    const float* out_proj_w = (const float*)d_in[12];
    const float* norm_w     = (const float*)d_in[13];
    const float* norm_b     = (const float*)d_in[14];
    const float* fw         = (const float*)d_in[15];
    const float* fb         = (const float*)d_in[16];
    const unsigned char* mask = (const unsigned char*)d_in[17];

    float *tok, *h, *xz, *xc, *dbl, *y;
    cudaGetSymbolAddress((void**)&tok, g_tok);
    cudaGetSymbolAddress((void**)&h,   g_h);
    cudaGetSymbolAddress((void**)&xz,  g_xz);
    cudaGetSymbolAddress((void**)&xc,  g_xc);
    cudaGetSymbolAddress((void**)&dbl, g_dbl);
    cudaGetSymbolAddress((void**)&y,   g_y);

    sgemm_patch_k<<<dim3(D / 64, NTOK / 64), 256>>>(x, patch_w, tok, patch_b);
    posembed_k<<<NTOK, D>>>(bp, mask);

    for (int layer = 0; layer < DEPTH; layer++) {
        ln_k<<<NTOK, 128>>>(tok, h, norm_w + layer * D, norm_b + layer * D, dbl);
        sgemm_k<<<dim3((2 * D) / 64, NTOK / 64, 1), 256>>>(h, D,
                in_proj_w + (size_t)layer * D * 2 * D, xz, nullptr, NTOK, 2 * D, D, 0);
        conv_k<<<NTOK, D>>>(conv_w + (size_t)layer * D * 4, conv_b + (size_t)layer * D);
        sgemm_k<<<dim3(1, NTOK / 64, 4), 256>>>(xc, D,
                x_proj_w + (size_t)layer * D * DBL_N, dbl, nullptr, NTOK, DBL_N, D, 0);
        scan_k<<<B_SZ * D, 128>>>(A_log + (size_t)layer * D * DSTATE,
                                  dt_proj_w + (size_t)layer * DTRANK * D,
                                  dt_proj_b + (size_t)layer * D,
                                  Dskip + (size_t)layer * D);
        sgemm_k<<<dim3(D / 64, NTOK / 64, 1), 256>>>(y, D,
                out_proj_w + (size_t)layer * D * D, tok, nullptr, NTOK, D, D, 3);
    }

    ln_k<<<NTOK, 128>>>(tok, (float*)d_out, fw, fb, nullptr);
}

// round 9
// speedup vs baseline: 1.2525x; 1.0123x over previous
#include <cuda_runtime.h>
#include <math.h>
#include <stdint.h>

#define B_SZ 2
#define L 1024
#define D 384
#define PATCH_DIM 4096
#define DEPTH 12
#define DSTATE 16
#define DTRANK 24
#define DBL_N 56
#define NTOK (B_SZ * L)   // 2048
#define NCH 8             // scan chunks
#define CHL (L / NCH)     // 128 steps per chunk

typedef unsigned long long ull;

// ------------------------- scratch (static device) -------------------------
__device__ float g_tok[NTOK * D];
__device__ float g_h[NTOK * D];
__device__ float g_xz[NTOK * 2 * D];
__device__ float g_xc[NTOK * D];
__device__ float g_dbl[NTOK * DBL_N];
__device__ float g_y[NTOK * D];

// ------------------------- cp.async + f32x2 helpers ------------------------
__device__ __forceinline__ void cp_async16(uint32_t dst, const void* src, bool pred) {
    int sz = pred ? 16 : 0;
    asm volatile("cp.async.ca.shared.global [%0], [%1], 16, %2;\n"
                 :: "r"(dst), "l"(src), "r"(sz));
}
__device__ __forceinline__ void cp_commit() {
    asm volatile("cp.async.commit_group;\n");
}
template <int N>
__device__ __forceinline__ void cp_wait() {
    asm volatile("cp.async.wait_group %0;\n" :: "n"(N));
}
__device__ __forceinline__ ull pack2(float x, float y) {
    ull r; asm("mov.b64 %0, {%1, %2};" : "=l"(r) : "f"(x), "f"(y)); return r;
}
__device__ __forceinline__ void unpack2(ull v, float& x, float& y) {
    asm("mov.b64 {%0, %1}, %2;" : "=f"(x), "=f"(y) : "l"(v));
}
__device__ __forceinline__ void ffma2(ull& d, ull a, ull b) {
    asm("fma.rn.f32x2 %0, %1, %2, %0;" : "+l"(d) : "l"(a), "l"(b));
}

// ------------------------- pipelined SGEMM 64x64, 3-stage ring -------------
#define BM 64
#define BN 64
#define BK 16
#define ASTRIDE 20   // 80 B row stride: 16B-aligned

struct SmemGemm {
    __align__(16) float As[3][BM * ASTRIDE];
    __align__(16) float Bs[3][BK * BN];
};

// inner microkernel: kk blocked by 4, A read as LDS.128 along k
__device__ __forceinline__ void gemm_inner(const float* __restrict__ As,
                                           const float* __restrict__ Bsr,
                                           int m0, int n0, ull acc2[4][2])
{
    #pragma unroll
    for (int k4 = 0; k4 < BK; k4 += 4) {
        float4 a[4];
        #pragma unroll
        for (int i = 0; i < 4; i++)
            a[i] = *reinterpret_cast<const float4*>(&As[(m0 + i) * ASTRIDE + k4]);
        #pragma unroll
        for (int q = 0; q < 4; q++) {
            float4 bq = *reinterpret_cast<const float4*>(&Bsr[(k4 + q) * BN + n0]);
            ull b01 = pack2(bq.x, bq.y);
            ull b23 = pack2(bq.z, bq.w);
            #pragma unroll
            for (int i = 0; i < 4; i++) {
                const float* af = &a[i].x;
                ull ap = pack2(af[q], af[q]);
                ffma2(acc2[i][0], ap, b01);
                ffma2(acc2[i][1], ap, b23);
            }
        }
    }
}

// epi: 0 none, 1 +bias, 3 C += result. gridDim.z>1 -> split-K atomicAdd.
__global__ void __launch_bounds__(256, 3)
sgemm_k(const float* __restrict__ A, int lda,
        const float* __restrict__ Bm,
        float* __restrict__ C,
        const float* __restrict__ bias,
        int M, int N, int K, int epi)
{
    __shared__ SmemGemm sm;
    const int bm = blockIdx.y * BM, bn = blockIdx.x * BN;
    const int tid = threadIdx.x;

    const int ksplit = gridDim.z;
    const int kc = K / ksplit;
    const int kstart = blockIdx.z * kc;
    const int kend = kstart + kc;
    const int niters = (kc + BK - 1) / BK;

    const int am  = tid >> 2;
    const int akq = (tid & 3) << 2;
    const int bkb = tid >> 4;
    const int bn4 = (tid & 15) << 2;
    const bool bn_ok = (bn + bn4) < N;

    const float* Arow = A + (size_t)(bm + am) * lda;

    uint32_t sAs = (uint32_t)__cvta_generic_to_shared(&sm.As[0][0]);
    uint32_t sBs = (uint32_t)__cvta_generic_to_shared(&sm.Bs[0][0]);

    auto load_stage = [&](int it, int buf) {
        int k0 = kstart + it * BK;
        {
            int k = k0 + akq;
            bool p = k < kend;
            const float* src = p ? (Arow + k) : A;
            cp_async16(sAs + (buf * BM * ASTRIDE + am * ASTRIDE + akq) * 4, src, p);
        }
        {
            int k = k0 + bkb;
            bool p = (k < kend) && bn_ok;
            const float* src = p ? (Bm + (size_t)k * N + bn + bn4) : Bm;
            cp_async16(sBs + (buf * BK * BN + bkb * BN + bn4) * 4, src, p);
        }
        cp_commit();
    };

    const int ty = tid >> 4, tx = tid & 15;
    const int m0 = ty * 4, n0 = tx * 4;

    ull acc2[4][2];
    #pragma unroll
    for (int i = 0; i < 4; i++) { acc2[i][0] = 0ull; acc2[i][1] = 0ull; }

    load_stage(0, 0);
    if (niters > 1) load_stage(1, 1);

    int buf = 0;
    for (int it = 0; it < niters; it++) {
        cp_wait<1>();
        __syncthreads();
        if (it + 2 < niters) {
            int nb = buf - 1; if (nb < 0) nb += 3;   // (it+2) % 3
            load_stage(it + 2, nb);
        }
        gemm_inner(&sm.As[buf][0], &sm.Bs[buf][0], m0, n0, acc2);
        buf++; if (buf == 3) buf = 0;
    }

    #pragma unroll
    for (int i = 0; i < 4; i++) {
        int row = bm + m0 + i;
        float v[4];
        unpack2(acc2[i][0], v[0], v[1]);
        unpack2(acc2[i][1], v[2], v[3]);
        #pragma unroll
        for (int j = 0; j < 4; j++) {
            int col = bn + n0 + j;
            if (col < N) {
                size_t off = (size_t)row * N + col;
                float vv = v[j];
                if (ksplit > 1) {
                    atomicAdd(&C[off], vv);
                } else {
                    if (epi == 1) vv += bias[col];
                    if (epi == 3) vv += C[off];
                    C[off] = vv;
                }
            }
        }
    }
}

// ------------------------- patchify GEMM (im2col fused) --------------------
__global__ void __launch_bounds__(256, 3)
sgemm_patch_k(const float* __restrict__ X,
              const float* __restrict__ Bm,
              float* __restrict__ C,
              const float* __restrict__ bias)
{
    __shared__ SmemGemm sm;
    const int bm = blockIdx.y * BM, bn = blockIdx.x * BN;
    const int tid = threadIdx.x;
    const int N = D, K = PATCH_DIM;
    const int niters = K / BK;

    const int am  = tid >> 2;
    const int akq = (tid & 3) << 2;
    const int bkb = tid >> 4;
    const int bn4 = (tid & 15) << 2;

    const int m = bm + am;
    const int b = m >> 10, l = m & 1023;
    const int gh = l >> 6, gw = (l >> 3) & 7, gd = l & 7;
    const size_t xbase = ((size_t)(b * 256 + gh * 16) * 256 + gw * 32) * 64 + gd * 8;

    uint32_t sAs = (uint32_t)__cvta_generic_to_shared(&sm.As[0][0]);
    uint32_t sBs = (uint32_t)__cvta_generic_to_shared(&sm.Bs[0][0]);

    auto load_stage = [&](int it, int buf) {
        int k0 = it * BK;
        {
            int k = k0 + akq;
            int ph = k >> 8, pw = (k >> 3) & 31, pd = k & 7;
            const float* src = X + xbase + (size_t)ph * 16384 + pw * 64 + pd;
            cp_async16(sAs + (buf * BM * ASTRIDE + am * ASTRIDE + akq) * 4, src, true);
        }
        {
            int k = k0 + bkb;
            const float* src = Bm + (size_t)k * N + bn + bn4;
            cp_async16(sBs + (buf * BK * BN + bkb * BN + bn4) * 4, src, true);
        }
        cp_commit();
    };

    const int ty = tid >> 4, tx = tid & 15;
    const int m0 = ty * 4, n0 = tx * 4;

    ull acc2[4][2];
    #pragma unroll
    for (int i = 0; i < 4; i++) { acc2[i][0] = 0ull; acc2[i][1] = 0ull; }

    load_stage(0, 0);
    load_stage(1, 1);

    int buf = 0;
    for (int it = 0; it < niters; it++) {
        cp_wait<1>();
        __syncthreads();
        if (it + 2 < niters) {
            int nb = buf - 1; if (nb < 0) nb += 3;
            load_stage(it + 2, nb);
        }
        gemm_inner(&sm.As[buf][0], &sm.Bs[buf][0], m0, n0, acc2);
        buf++; if (buf == 3) buf = 0;
    }

    #pragma unroll
    for (int i = 0; i < 4; i++) {
        int row = bm + m0 + i;
        float v[4];
        unpack2(acc2[i][0], v[0], v[1]);
        unpack2(acc2[i][1], v[2], v[3]);
        #pragma unroll
        for (int j = 0; j < 4; j++) {
            int col = bn + n0 + j;
            C[(size_t)row * N + col] = v[j] + bias[col];
        }
    }
}

// ------------------------- LayerNorm (row of 384) + dbl zeroing ------------
__global__ void ln_k(const float* __restrict__ in, float* __restrict__ out,
                     const float* __restrict__ w, const float* __restrict__ b,
                     float* __restrict__ zbuf)
{
    int row = blockIdx.x;
    int t = threadIdx.x;   // 128 threads
    if (zbuf != nullptr && t < DBL_N) zbuf[(size_t)row * DBL_N + t] = 0.f;
    const float* r = in + (size_t)row * D;
    float v0 = r[t], v1 = r[t + 128], v2 = r[t + 256];
    float s = v0 + v1 + v2;
    __shared__ float sh[4], sh2[4];
    #pragma unroll
    for (int o = 16; o; o >>= 1) s += __shfl_xor_sync(~0u, s, o);
    if ((t & 31) == 0) sh[t >> 5] = s;
    __syncthreads();
    float mu = (sh[0] + sh[1] + sh[2] + sh[3]) * (1.f / 384.f);
    float d0 = v0 - mu, d1 = v1 - mu, d2 = v2 - mu;
    float q = d0 * d0 + d1 * d1 + d2 * d2;
    #pragma unroll
    for (int o = 16; o; o >>= 1) q += __shfl_xor_sync(~0u, q, o);
    if ((t & 31) == 0) sh2[t >> 5] = q;
    __syncthreads();
    float var = (sh2[0] + sh2[1] + sh2[2] + sh2[3]) * (1.f / 384.f);
    float rs = rsqrtf(var + 1e-5f);
    float* o = out + (size_t)row * D;
    o[t]       = d0 * rs * w[t]       + b[t];
    o[t + 128] = d1 * rs * w[t + 128] + b[t + 128];
    o[t + 256] = d2 * rs * w[t + 256] + b[t + 256];
}

// ------------------------- positional embedding ----------------------------
__global__ void posembed_k(const float* __restrict__ bp,
                           const unsigned char* __restrict__ mask)
{
    int row = blockIdx.x;           // NTOK
    int d = threadIdx.x;            // 384
    int b = row >> 10, l = row & 1023;
    int gh = l >> 6, gw = (l >> 3) & 7, gd = l & 7;
    float vr = bp[b * 4 + 2];
    bool m = mask[b] != 0;
    int j = d / 128, r = d - j * 128, f = r & 63;
    float c;
    if (j == 0)      c = (float)gh * (1.f / 15.f);
    else if (j == 1) c = ((float)gw - 4.f) * 0.25f;
    else {
        float v = m ? ((float)gd - 4.f) * vr : (float)gd * vr;
        float den = m ? 4.f * vr : 7.f * vr;
        c = v / den;
    }
    float omega = powf(10000.f, -(float)f * (1.f / 64.f));
    float ph = c * omega;
    g_tok[(size_t)row * D + d] += (r < 64) ? sinf(ph) : cosf(ph);
}

// ------------------------- causal depthwise conv + silu --------------------
__global__ void conv_k(const float* __restrict__ cw, const float* __restrict__ cb)
{
    int row = blockIdx.x;           // NTOK
    int d = threadIdx.x;            // 384
    int l = row & 1023, b = row >> 10;
    float acc = cb[d];
    #pragma unroll
    for (int j = 0; j < 4; j++) {
        int ll = l - 3 + j;
        if (ll >= 0)
            acc = fmaf(g_xz[(size_t)((b << 10) + ll) * (2 * D) + d], cw[d * 4 + j], acc);
    }
    g_xc[(size_t)row * D + d] = acc / (1.f + __expf(-acc));
}

// ------------------------- fused chunked selective scan --------------------
__global__ void scan_k(const float* __restrict__ A_log,
                       const float* __restrict__ dtw,
                       const float* __restrict__ dtb,
                       const float* __restrict__ Dsk)
{
    __shared__ float s_dt[L];
    __shared__ float s_xc[L];
    __shared__ float s_P[NCH][DSTATE];
    __shared__ float s_W[NCH][DSTATE];

    const int tid = threadIdx.x;    // 128
    const int blk = blockIdx.x;     // 0..767
    const int b = blk / D;
    const int d = blk - b * D;

    // ---- phase A: dt + xc stash ----
    float wreg[DTRANK];
    #pragma unroll
    for (int r = 0; r < DTRANK; r++) wreg[r] = __ldg(&dtw[r * D + d]);
    const float bias = __ldg(&dtb[d]);
    const float* dbl_b = g_dbl + (size_t)b * L * DBL_N;
    const float* xc_g  = g_xc + (size_t)b * L * D + d;

    #pragma unroll
    for (int i = 0; i < L / 128; i++) {
        int l = tid + i * 128;
        const float* row = dbl_b + (size_t)l * DBL_N;
        float acc = bias;
        #pragma unroll
        for (int r = 0; r < DTRANK; r++) acc = fmaf(__ldg(row + r), wreg[r], acc);
        s_dt[l] = (acc > 20.f) ? acc : log1pf(__expf(acc));
        s_xc[l] = __ldg(xc_g + (size_t)l * D);
    }
    __syncthreads();

    // ---- phase B: per-chunk local scan ----
    const int u = tid >> 4, lane = tid & 15;
    const float Aa = -__expf(A_log[d * DSTATE + lane]);
    const float* B_g = dbl_b + DTRANK + lane;
    const int l0 = u * CHL;

    float h = 0.f, P = 1.f;
    #pragma unroll 4
    for (int l = 0; l < CHL; l++) {
        float dtv = s_dt[l0 + l];
        float uv  = s_xc[l0 + l];
        float Bv  = __ldg(B_g + (size_t)(l0 + l) * DBL_N);
        float dA  = __expf(dtv * Aa);
        h = fmaf(h, dA, dtv * uv * Bv);
        P *= dA;
    }
    s_P[u][lane] = P;
    s_W[u][lane] = h;
    __syncthreads();

    // ---- phase C: prefix fold ----
    h = 0.f;
    for (int j = 0; j < u; j++)
        h = fmaf(h, s_P[j][lane], s_W[j][lane]);

    // ---- phase D: replay with output ----
    const float Dp = __ldg(&Dsk[d]);
    const float* z_g = g_xz + (size_t)b * L * (2 * D) + D + d;
    float* y_g = g_y + (size_t)b * L * D + d;

    #pragma unroll 4
    for (int l = 0; l < CHL; l++) {
        int ll = l0 + l;
        float dtv = s_dt[ll];
        float uv  = s_xc[ll];
        float Bv  = __ldg(B_g + (size_t)ll * DBL_N);
        float Cv  = __ldg(B_g + (size_t)ll * DBL_N + DSTATE);
        float dA  = __expf(dtv * Aa);
        h = fmaf(h, dA, dtv * uv * Bv);
        float p = h * Cv;
        p += __shfl_xor_sync(0xffffffffu, p, 8);
        p += __shfl_xor_sync(0xffffffffu, p, 4);
        p += __shfl_xor_sync(0xffffffffu, p, 2);
        p += __shfl_xor_sync(0xffffffffu, p, 1);
        if (lane == 0) {
            float zv = __ldg(z_g + (size_t)ll * 2 * D);
            float sz = zv / (1.f + __expf(-zv));
            y_g[(size_t)ll * D] = (p + uv * Dp) * sz;
        }
    }
}

// ------------------------- launch ------------------------------------------
extern "C" void kernel_launch(void* const* d_in, const int* in_sizes, int n_in,
                              void* d_out, int out_size)
{
    const float* x          = (const float*)d_in[0];
    const float* bp         = (const float*)d_in[1];
    const float* patch_w    = (const float*)d_in[2];
    const float* patch_b    = (const float*)d_in[3];
    const float* in_proj_w  = (const float*)d_in[4];
    const float* conv_w     = (const float*)d_in[5];
    const float* conv_b     = (const float*)d_in[6];
    const float* x_proj_w   = (const float*)d_in[7];
    const float* dt_proj_w  = (const float*)d_in[8];
    const float* dt_proj_b  = (const float*)d_in[9];
    const float* A_log      = (const float*)d_in[10];
    const float* Dskip      = (const float*)d_in[11];
    const float* out_proj_w = (const float*)d_in[12];
    const float* norm_w     = (const float*)d_in[13];
    const float* norm_b     = (const float*)d_in[14];
    const float* fw         = (const float*)d_in[15];
    const float* fb         = (const float*)d_in[16];
    const unsigned char* mask = (const unsigned char*)d_in[17];

    float *tok, *h, *xz, *xc, *dbl, *y;
    cudaGetSymbolAddress((void**)&tok, g_tok);
    cudaGetSymbolAddress((void**)&h,   g_h);
    cudaGetSymbolAddress((void**)&xz,  g_xz);
    cudaGetSymbolAddress((void**)&xc,  g_xc);
    cudaGetSymbolAddress((void**)&dbl, g_dbl);
    cudaGetSymbolAddress((void**)&y,   g_y);

    sgemm_patch_k<<<dim3(D / 64, NTOK / 64), 256>>>(x, patch_w, tok, patch_b);
    posembed_k<<<NTOK, D>>>(bp, mask);

    for (int layer = 0; layer < DEPTH; layer++) {
        ln_k<<<NTOK, 128>>>(tok, h, norm_w + layer * D, norm_b + layer * D, dbl);
        sgemm_k<<<dim3((2 * D) / 64, NTOK / 64, 1), 256>>>(h, D,
                in_proj_w + (size_t)layer * D * 2 * D, xz, nullptr, NTOK, 2 * D, D, 0);
        conv_k<<<NTOK, D>>>(conv_w + (size_t)layer * D * 4, conv_b + (size_t)layer * D);
        sgemm_k<<<dim3(1, NTOK / 64, 4), 256>>>(xc, D,
                x_proj_w + (size_t)layer * D * DBL_N, dbl, nullptr, NTOK, DBL_N, D, 0);
        scan_k<<<B_SZ * D, 128>>>(A_log + (size_t)layer * D * DSTATE,
                                  dt_proj_w + (size_t)layer * DTRANK * D,
                                  dt_proj_b + (size_t)layer * D,
                                  Dskip + (size_t)layer * D);
        sgemm_k<<<dim3(D / 64, NTOK / 64, 1), 256>>>(y, D,
                out_proj_w + (size_t)layer * D * D, tok, nullptr, NTOK, D, D, 3);
    }

    ln_k<<<NTOK, 128>>>(tok, (float*)d_out, fw, fb, nullptr);
}

// round 10
// speedup vs baseline: 1.7630x; 1.4077x over previous
#include <cuda_runtime.h>
#include <math.h>
#include <stdint.h>

#define B_SZ 2
#define L 1024
#define D 384
#define PATCH_DIM 4096
#define DEPTH 12
#define DSTATE 16
#define DTRANK 24
#define DBL_N 56
#define NTOK (B_SZ * L)   // 2048
#define NCH 8             // scan chunks
#define CHL (L / NCH)     // 128 steps per chunk
#define SCH 8             // chains per scan block

typedef unsigned long long ull;

// ------------------------- scratch (static device) -------------------------
__device__ float g_tok[NTOK * D];
__device__ float g_h[NTOK * D];
__device__ float g_xz[NTOK * 2 * D];
__device__ float g_xc[NTOK * D];
__device__ float g_dbl[NTOK * DBL_N];
__device__ float g_dt[NTOK * D];
__device__ float g_y[NTOK * D];
__device__ float g_P[B_SZ * D * NCH * DSTATE];
__device__ float g_W[B_SZ * D * NCH * DSTATE];

// ------------------------- cp.async + f32x2 helpers ------------------------
__device__ __forceinline__ void cp_async16(uint32_t dst, const void* src, bool pred) {
    int sz = pred ? 16 : 0;
    asm volatile("cp.async.ca.shared.global [%0], [%1], 16, %2;\n"
                 :: "r"(dst), "l"(src), "r"(sz));
}
__device__ __forceinline__ void cp_commit() {
    asm volatile("cp.async.commit_group;\n");
}
template <int N>
__device__ __forceinline__ void cp_wait() {
    asm volatile("cp.async.wait_group %0;\n" :: "n"(N));
}
__device__ __forceinline__ ull pack2(float x, float y) {
    ull r; asm("mov.b64 %0, {%1, %2};" : "=l"(r) : "f"(x), "f"(y)); return r;
}
__device__ __forceinline__ void unpack2(ull v, float& x, float& y) {
    asm("mov.b64 {%0, %1}, %2;" : "=f"(x), "=f"(y) : "l"(v));
}
__device__ __forceinline__ void ffma2(ull& d, ull a, ull b) {
    asm("fma.rn.f32x2 %0, %1, %2, %0;" : "+l"(d) : "l"(a), "l"(b));
}

// ------------------------- pipelined SGEMM 64x64 (vector LDS + FFMA2) ------
#define BM 64
#define BN 64
#define BK 16
#define ASTRIDE 20

struct SmemGemm {
    __align__(16) float As[2][BM * ASTRIDE];
    __align__(16) float Bs[2][BK * BN];
};

__device__ __forceinline__ void gemm_inner(const float* __restrict__ As,
                                           const float* __restrict__ Bsr,
                                           int m0, int n0, ull acc2[4][2])
{
    #pragma unroll
    for (int k4 = 0; k4 < BK; k4 += 4) {
        float4 a[4];
        #pragma unroll
        for (int i = 0; i < 4; i++)
            a[i] = *reinterpret_cast<const float4*>(&As[(m0 + i) * ASTRIDE + k4]);
        #pragma unroll
        for (int q = 0; q < 4; q++) {
            float4 bq = *reinterpret_cast<const float4*>(&Bsr[(k4 + q) * BN + n0]);
            ull b01 = pack2(bq.x, bq.y);
            ull b23 = pack2(bq.z, bq.w);
            #pragma unroll
            for (int i = 0; i < 4; i++) {
                const float* af = &a[i].x;
                ull ap = pack2(af[q], af[q]);
                ffma2(acc2[i][0], ap, b01);
                ffma2(acc2[i][1], ap, b23);
            }
        }
    }
}

// epi: 0 none, 1 +bias, 2 +bias->softplus, 3 C += result.
// gridDim.z>1 -> split-K atomicAdd (epi must be 0).
__global__ void sgemm_k(const float* __restrict__ A, int lda,
                        const float* __restrict__ Bm,
                        float* __restrict__ C,
                        const float* __restrict__ bias,
                        int M, int N, int K, int epi)
{
    __shared__ SmemGemm sm;
    const int bm = blockIdx.y * BM, bn = blockIdx.x * BN;
    const int tid = threadIdx.x;

    const int ksplit = gridDim.z;
    const int kc = K / ksplit;
    const int kstart = blockIdx.z * kc;
    const int kend = kstart + kc;
    const int niters = (kc + BK - 1) / BK;

    const int am  = tid >> 2;
    const int akq = (tid & 3) << 2;
    const int bkb = tid >> 4;
    const int bn4 = (tid & 15) << 2;
    const bool bn_ok = (bn + bn4) < N;

    const float* Arow = A + (size_t)(bm + am) * lda;

    uint32_t sAs = (uint32_t)__cvta_generic_to_shared(&sm.As[0][0]);
    uint32_t sBs = (uint32_t)__cvta_generic_to_shared(&sm.Bs[0][0]);

    auto load_stage = [&](int it, int buf) {
        int k0 = kstart + it * BK;
        {
            int k = k0 + akq;
            bool p = k < kend;
            const float* src = p ? (Arow + k) : A;
            cp_async16(sAs + (buf * BM * ASTRIDE + am * ASTRIDE + akq) * 4, src, p);
        }
        {
            int k = k0 + bkb;
            bool p = (k < kend) && bn_ok;
            const float* src = p ? (Bm + (size_t)k * N + bn + bn4) : Bm;
            cp_async16(sBs + (buf * BK * BN + bkb * BN + bn4) * 4, src, p);
        }
    };

    const int ty = tid >> 4, tx = tid & 15;
    const int m0 = ty * 4, n0 = tx * 4;

    ull acc2[4][2];
    #pragma unroll
    for (int i = 0; i < 4; i++) { acc2[i][0] = 0ull; acc2[i][1] = 0ull; }

    load_stage(0, 0); cp_commit();
    if (niters > 1) load_stage(1, 1);
    cp_commit();

    for (int it = 0; it < niters; it++) {
        cp_wait<1>();
        __syncthreads();
        const int buf = it & 1;
        gemm_inner(&sm.As[buf][0], &sm.Bs[buf][0], m0, n0, acc2);
        __syncthreads();
        if (it + 2 < niters) load_stage(it + 2, buf);
        cp_commit();
    }

    #pragma unroll
    for (int i = 0; i < 4; i++) {
        int row = bm + m0 + i;
        float v[4];
        unpack2(acc2[i][0], v[0], v[1]);
        unpack2(acc2[i][1], v[2], v[3]);
        #pragma unroll
        for (int j = 0; j < 4; j++) {
            int col = bn + n0 + j;
            if (col < N) {
                size_t off = (size_t)row * N + col;
                float vv = v[j];
                if (ksplit > 1) {
                    atomicAdd(&C[off], vv);
                } else {
                    if (epi == 1 || epi == 2) vv += bias[col];
                    if (epi == 2) vv = (vv > 20.f) ? vv : log1pf(__expf(vv));
                    if (epi == 3) vv += C[off];
                    C[off] = vv;
                }
            }
        }
    }
}

// ------------------------- patchify GEMM (im2col fused) --------------------
__global__ void sgemm_patch_k(const float* __restrict__ X,
                              const float* __restrict__ Bm,
                              float* __restrict__ C,
                              const float* __restrict__ bias)
{
    __shared__ SmemGemm sm;
    const int bm = blockIdx.y * BM, bn = blockIdx.x * BN;
    const int tid = threadIdx.x;
    const int N = D, K = PATCH_DIM;
    const int niters = K / BK;

    const int am  = tid >> 2;
    const int akq = (tid & 3) << 2;
    const int bkb = tid >> 4;
    const int bn4 = (tid & 15) << 2;

    const int m = bm + am;
    const int b = m >> 10, l = m & 1023;
    const int gh = l >> 6, gw = (l >> 3) & 7, gd = l & 7;
    const size_t xbase = ((size_t)(b * 256 + gh * 16) * 256 + gw * 32) * 64 + gd * 8;

    uint32_t sAs = (uint32_t)__cvta_generic_to_shared(&sm.As[0][0]);
    uint32_t sBs = (uint32_t)__cvta_generic_to_shared(&sm.Bs[0][0]);

    auto load_stage = [&](int it, int buf) {
        int k0 = it * BK;
        {
            int k = k0 + akq;
            int ph = k >> 8, pw = (k >> 3) & 31, pd = k & 7;
            const float* src = X + xbase + (size_t)ph * 16384 + pw * 64 + pd;
            cp_async16(sAs + (buf * BM * ASTRIDE + am * ASTRIDE + akq) * 4, src, true);
        }
        {
            int k = k0 + bkb;
            const float* src = Bm + (size_t)k * N + bn + bn4;
            cp_async16(sBs + (buf * BK * BN + bkb * BN + bn4) * 4, src, true);
        }
    };

    const int ty = tid >> 4, tx = tid & 15;
    const int m0 = ty * 4, n0 = tx * 4;

    ull acc2[4][2];
    #pragma unroll
    for (int i = 0; i < 4; i++) { acc2[i][0] = 0ull; acc2[i][1] = 0ull; }

    load_stage(0, 0); cp_commit();
    load_stage(1, 1); cp_commit();

    for (int it = 0; it < niters; it++) {
        cp_wait<1>();
        __syncthreads();
        const int buf = it & 1;
        gemm_inner(&sm.As[buf][0], &sm.Bs[buf][0], m0, n0, acc2);
        __syncthreads();
        if (it + 2 < niters) load_stage(it + 2, buf);
        cp_commit();
    }

    #pragma unroll
    for (int i = 0; i < 4; i++) {
        int row = bm + m0 + i;
        float v[4];
        unpack2(acc2[i][0], v[0], v[1]);
        unpack2(acc2[i][1], v[2], v[3]);
        #pragma unroll
        for (int j = 0; j < 4; j++) {
            int col = bn + n0 + j;
            C[(size_t)row * N + col] = v[j] + bias[col];
        }
    }
}

// ------------------------- LayerNorm (row of 384) + dbl zeroing ------------
__global__ void ln_k(const float* __restrict__ in, float* __restrict__ out,
                     const float* __restrict__ w, const float* __restrict__ b,
                     float* __restrict__ zbuf)
{
    int row = blockIdx.x;
    int t = threadIdx.x;   // 128 threads
    if (zbuf != nullptr && t < DBL_N) zbuf[(size_t)row * DBL_N + t] = 0.f;
    const float* r = in + (size_t)row * D;
    float v0 = r[t], v1 = r[t + 128], v2 = r[t + 256];
    float s = v0 + v1 + v2;
    __shared__ float sh[4], sh2[4];
    #pragma unroll
    for (int o = 16; o; o >>= 1) s += __shfl_xor_sync(~0u, s, o);
    if ((t & 31) == 0) sh[t >> 5] = s;
    __syncthreads();
    float mu = (sh[0] + sh[1] + sh[2] + sh[3]) * (1.f / 384.f);
    float d0 = v0 - mu, d1 = v1 - mu, d2 = v2 - mu;
    float q = d0 * d0 + d1 * d1 + d2 * d2;
    #pragma unroll
    for (int o = 16; o; o >>= 1) q += __shfl_xor_sync(~0u, q, o);
    if ((t & 31) == 0) sh2[t >> 5] = q;
    __syncthreads();
    float var = (sh2[0] + sh2[1] + sh2[2] + sh2[3]) * (1.f / 384.f);
    float rs = rsqrtf(var + 1e-5f);
    float* o = out + (size_t)row * D;
    o[t]       = d0 * rs * w[t]       + b[t];
    o[t + 128] = d1 * rs * w[t + 128] + b[t + 128];
    o[t + 256] = d2 * rs * w[t + 256] + b[t + 256];
}

// ------------------------- positional embedding ----------------------------
__global__ void posembed_k(const float* __restrict__ bp,
                           const unsigned char* __restrict__ mask)
{
    int row = blockIdx.x;           // NTOK
    int d = threadIdx.x;            // 384
    int b = row >> 10, l = row & 1023;
    int gh = l >> 6, gw = (l >> 3) & 7, gd = l & 7;
    float vr = bp[b * 4 + 2];
    bool m = mask[b] != 0;
    int j = d / 128, r = d - j * 128, f = r & 63;
    float c;
    if (j == 0)      c = (float)gh * (1.f / 15.f);
    else if (j == 1) c = ((float)gw - 4.f) * 0.25f;
    else {
        float v = m ? ((float)gd - 4.f) * vr : (float)gd * vr;
        float den = m ? 4.f * vr : 7.f * vr;
        c = v / den;
    }
    float omega = powf(10000.f, -(float)f * (1.f / 64.f));
    float ph = c * omega;
    g_tok[(size_t)row * D + d] += (r < 64) ? sinf(ph) : cosf(ph);
}

// ------------------------- causal depthwise conv + silu --------------------
__global__ void conv_k(const float* __restrict__ cw, const float* __restrict__ cb)
{
    int row = blockIdx.x;           // NTOK
    int d = threadIdx.x;            // 384
    int l = row & 1023, b = row >> 10;
    float acc = cb[d];
    #pragma unroll
    for (int j = 0; j < 4; j++) {
        int ll = l - 3 + j;
        if (ll >= 0)
            acc = fmaf(g_xz[(size_t)((b << 10) + ll) * (2 * D) + d], cw[d * 4 + j], acc);
    }
    g_xc[(size_t)row * D + d] = acc / (1.f + __expf(-acc));
}

// ------------------------- chunked scan, smem-staged ------------------------
// Grid (96, NCH). Block = 8 chains (d0..d0+7) x 16 lanes = 128 threads,
// ONE chunk of 128 steps. All global reads staged coalesced via cp.async.
struct ScanTilePart {
    __align__(16) float dt[CHL][SCH];
    __align__(16) float xc[CHL][SCH];
    __align__(16) float bc[CHL][32];   // B[16] | C[16]
};
struct ScanTileFull {
    __align__(16) float dt[CHL][SCH];
    __align__(16) float xc[CHL][SCH];
    __align__(16) float bc[CHL][32];
    __align__(16) float zz[CHL][SCH];
    __align__(16) float yy[CHL][SCH];
};

__device__ __forceinline__ void scan_load_common(
    uint32_t s_dt, uint32_t s_xc, uint32_t s_bc,
    const float* dt_g, const float* xc_g, const float* dbl_b,
    int l0, int d0, int tid)
{
    // dt/xc: 256 txns each (row = q>>1, 16B part = q&1)
    #pragma unroll
    for (int q = 0; q < 2; q++) {
        int qq = tid + q * 128;
        int row = qq >> 1, part = (qq & 1) << 2;
        cp_async16(s_dt + (row * SCH + part) * 4,
                   dt_g + (size_t)(l0 + row) * D + d0 + part, true);
        cp_async16(s_xc + (row * SCH + part) * 4,
                   xc_g + (size_t)(l0 + row) * D + d0 + part, true);
    }
    // bc: 1024 txns (row = q>>3, part = q&7)
    #pragma unroll
    for (int q = 0; q < 8; q++) {
        int qq = tid + q * 128;
        int row = qq >> 3, part = (qq & 7) << 2;
        cp_async16(s_bc + (row * 32 + part) * 4,
                   dbl_b + (size_t)(l0 + row) * DBL_N + DTRANK + part, true);
    }
}

__global__ void scan_part_k(const float* __restrict__ A_log)
{
    __shared__ ScanTilePart sm;
    const int tid = threadIdx.x;
    const int grp = tid >> 4, lane = tid & 15;
    const int c = blockIdx.y;
    const int blk = blockIdx.x;             // 0..95
    const int b = blk / 48;
    const int d0 = (blk % 48) * SCH;
    const int d = d0 + grp;
    const int l0 = c * CHL;

    const float* dbl_b = g_dbl + (size_t)b * L * DBL_N;
    scan_load_common((uint32_t)__cvta_generic_to_shared(&sm.dt[0][0]),
                     (uint32_t)__cvta_generic_to_shared(&sm.xc[0][0]),
                     (uint32_t)__cvta_generic_to_shared(&sm.bc[0][0]),
                     g_dt + (size_t)b * L * D, g_xc + (size_t)b * L * D,
                     dbl_b, l0, d0, tid);
    cp_commit();

    const float Aa = -__expf(A_log[d * DSTATE + lane]);

    cp_wait<0>();
    __syncthreads();

    float h = 0.f, P = 1.f;
    #pragma unroll 8
    for (int l = 0; l < CHL; l++) {
        float dtv = sm.dt[l][grp];
        float uv  = sm.xc[l][grp];
        float Bv  = sm.bc[l][lane];
        float dA  = __expf(dtv * Aa);
        h = fmaf(h, dA, dtv * uv * Bv);
        P *= dA;
    }
    const int chain = b * D + d;
    g_P[((size_t)chain * NCH + c) * DSTATE + lane] = P;
    g_W[((size_t)chain * NCH + c) * DSTATE + lane] = h;
}

__global__ void scan_full_k(const float* __restrict__ A_log,
                            const float* __restrict__ Dsk)
{
    __shared__ ScanTileFull sm;
    const int tid = threadIdx.x;
    const int grp = tid >> 4, lane = tid & 15;
    const int c = blockIdx.y;
    const int blk = blockIdx.x;             // 0..95
    const int b = blk / 48;
    const int d0 = (blk % 48) * SCH;
    const int d = d0 + grp;
    const int l0 = c * CHL;

    const float* dbl_b = g_dbl + (size_t)b * L * DBL_N;
    scan_load_common((uint32_t)__cvta_generic_to_shared(&sm.dt[0][0]),
                     (uint32_t)__cvta_generic_to_shared(&sm.xc[0][0]),
                     (uint32_t)__cvta_generic_to_shared(&sm.bc[0][0]),
                     g_dt + (size_t)b * L * D, g_xc + (size_t)b * L * D,
                     dbl_b, l0, d0, tid);
    // zz tile
    {
        uint32_t s_zz = (uint32_t)__cvta_generic_to_shared(&sm.zz[0][0]);
        const float* z_g = g_xz + (size_t)b * L * (2 * D) + D;
        #pragma unroll
        for (int q = 0; q < 2; q++) {
            int qq = tid + q * 128;
            int row = qq >> 1, part = (qq & 1) << 2;
            cp_async16(s_zz + (row * SCH + part) * 4,
                       z_g + (size_t)(l0 + row) * (2 * D) + d0 + part, true);
        }
    }
    cp_commit();

    const float Aa = -__expf(A_log[d * DSTATE + lane]);
    const float Dp = __ldg(&Dsk[d]);
    const int chain = b * D + d;

    // prefix fold while tile loads
    float h = 0.f;
    const float* Pp = g_P + (size_t)chain * NCH * DSTATE + lane;
    const float* Wp = g_W + (size_t)chain * NCH * DSTATE + lane;
    for (int j = 0; j < c; j++)
        h = fmaf(h, Pp[(size_t)j * DSTATE], Wp[(size_t)j * DSTATE]);

    cp_wait<0>();
    __syncthreads();

    #pragma unroll 8
    for (int l = 0; l < CHL; l++) {
        float dtv = sm.dt[l][grp];
        float uv  = sm.xc[l][grp];
        float Bv  = sm.bc[l][lane];
        float Cv  = sm.bc[l][lane + 16];
        float dA  = __expf(dtv * Aa);
        h = fmaf(h, dA, dtv * uv * Bv);
        float p = h * Cv;
        p += __shfl_xor_sync(0xffffffffu, p, 8);
        p += __shfl_xor_sync(0xffffffffu, p, 4);
        p += __shfl_xor_sync(0xffffffffu, p, 2);
        p += __shfl_xor_sync(0xffffffffu, p, 1);
        if (lane == 0) {
            float zv = sm.zz[l][grp];
            float sz = zv / (1.f + __expf(-zv));
            sm.yy[l][grp] = (p + uv * Dp) * sz;
        }
    }
    __syncthreads();

    // coalesced y write-out: thread t handles row t (8 floats = 2 float4)
    float* y_g = g_y + (size_t)(b * L + l0 + tid) * D + d0;
    float4 v0 = *reinterpret_cast<const float4*>(&sm.yy[tid][0]);
    float4 v1 = *reinterpret_cast<const float4*>(&sm.yy[tid][4]);
    *reinterpret_cast<float4*>(y_g)     = v0;
    *reinterpret_cast<float4*>(y_g + 4) = v1;
}

// ------------------------- launch ------------------------------------------
extern "C" void kernel_launch(void* const* d_in, const int* in_sizes, int n_in,
                              void* d_out, int out_size)
{
    const float* x          = (const float*)d_in[0];
    const float* bp         = (const float*)d_in[1];
    const float* patch_w    = (const float*)d_in[2];
    const float* patch_b    = (const float*)d_in[3];
    const float* in_proj_w  = (const float*)d_in[4];
    const float* conv_w     = (const float*)d_in[5];
    const float* conv_b     = (const float*)d_in[6];
    const float* x_proj_w   = (const float*)d_in[7];
    const float* dt_proj_w  = (const float*)d_in[8];
    const float* dt_proj_b  = (const float*)d_in[9];
    const float* A_log      = (const float*)d_in[10];
    const float* Dskip      = (const float*)d_in[11];
    const float* out_proj_w = (const float*)d_in[12];
    const float* norm_w     = (const float*)d_in[13];
    const float* norm_b     = (const float*)d_in[14];
    const float* fw         = (const float*)d_in[15];
    const float* fb         = (const float*)d_in[16];
    const unsigned char* mask = (const unsigned char*)d_in[17];

    float *tok, *h, *xz, *xc, *dbl, *dt, *y;
    cudaGetSymbolAddress((void**)&tok, g_tok);
    cudaGetSymbolAddress((void**)&h,   g_h);
    cudaGetSymbolAddress((void**)&xz,  g_xz);
    cudaGetSymbolAddress((void**)&xc,  g_xc);
    cudaGetSymbolAddress((void**)&dbl, g_dbl);
    cudaGetSymbolAddress((void**)&dt,  g_dt);
    cudaGetSymbolAddress((void**)&y,   g_y);

    sgemm_patch_k<<<dim3(D / 64, NTOK / 64), 256>>>(x, patch_w, tok, patch_b);
    posembed_k<<<NTOK, D>>>(bp, mask);

    for (int layer = 0; layer < DEPTH; layer++) {
        ln_k<<<NTOK, 128>>>(tok, h, norm_w + layer * D, norm_b + layer * D, dbl);
        sgemm_k<<<dim3((2 * D) / 64, NTOK / 64, 1), 256>>>(h, D,
                in_proj_w + (size_t)layer * D * 2 * D, xz, nullptr, NTOK, 2 * D, D, 0);
        conv_k<<<NTOK, D>>>(conv_w + (size_t)layer * D * 4, conv_b + (size_t)layer * D);
        sgemm_k<<<dim3(1, NTOK / 64, 4), 256>>>(xc, D,
                x_proj_w + (size_t)layer * D * DBL_N, dbl, nullptr, NTOK, DBL_N, D, 0);
        sgemm_k<<<dim3(D / 64, NTOK / 64, 1), 256>>>(dbl, DBL_N,
                dt_proj_w + (size_t)layer * DTRANK * D, dt, dt_proj_b + (size_t)layer * D,
                NTOK, D, DTRANK, 2);
        scan_part_k<<<dim3(96, NCH), 128>>>(A_log + (size_t)layer * D * DSTATE);
        scan_full_k<<<dim3(96, NCH), 128>>>(A_log + (size_t)layer * D * DSTATE,
                                            Dskip + (size_t)layer * D);
        sgemm_k<<<dim3(D / 64, NTOK / 64, 1), 256>>>(y, D,
                out_proj_w + (size_t)layer * D * D, tok, nullptr, NTOK, D, D, 3);
    }

    ln_k<<<NTOK, 128>>>(tok, (float*)d_out, fw, fb, nullptr);
}

// round 11
// speedup vs baseline: 1.9010x; 1.0783x over previous
#include <cuda_runtime.h>
#include <math.h>
#include <stdint.h>

#define B_SZ 2
#define L 1024
#define D 384
#define PATCH_DIM 4096
#define DEPTH 12
#define DSTATE 16
#define DTRANK 24
#define DBL_N 56
#define NTOK (B_SZ * L)   // 2048
#define NCH 8             // scan chunks
#define CHL (L / NCH)     // 128 steps per chunk
#define SCH 8             // chains per scan block

typedef unsigned long long ull;

// ------------------------- scratch (static device) -------------------------
__device__ float g_tok[NTOK * D];
__device__ float g_h[NTOK * D];
__device__ float g_xz[NTOK * 2 * D];
__device__ float g_xc[NTOK * D];
__device__ float g_dbl[NTOK * DBL_N];
__device__ float g_dt[NTOK * D];
__device__ float g_y[NTOK * D];
__device__ float g_P[B_SZ * D * NCH * DSTATE];
__device__ float g_W[B_SZ * D * NCH * DSTATE];

// ------------------------- cp.async + f32x2 helpers ------------------------
__device__ __forceinline__ void cp_async16(uint32_t dst, const void* src, bool pred) {
    int sz = pred ? 16 : 0;
    asm volatile("cp.async.ca.shared.global [%0], [%1], 16, %2;\n"
                 :: "r"(dst), "l"(src), "r"(sz));
}
__device__ __forceinline__ void cp_commit() {
    asm volatile("cp.async.commit_group;\n");
}
template <int N>
__device__ __forceinline__ void cp_wait() {
    asm volatile("cp.async.wait_group %0;\n" :: "n"(N));
}
__device__ __forceinline__ ull pack2(float x, float y) {
    ull r; asm("mov.b64 %0, {%1, %2};" : "=l"(r) : "f"(x), "f"(y)); return r;
}
__device__ __forceinline__ void unpack2(ull v, float& x, float& y) {
    asm("mov.b64 {%0, %1}, %2;" : "=f"(x), "=f"(y) : "l"(v));
}
__device__ __forceinline__ void ffma2(ull& d, ull a, ull b) {
    asm("fma.rn.f32x2 %0, %1, %2, %0;" : "+l"(d) : "l"(a), "l"(b));
}

// ------------------------- pipelined SGEMM 64x64 (vector LDS + FFMA2) ------
#define BM 64
#define BN 64
#define BK 16
#define ASTRIDE 20

struct SmemGemm {
    __align__(16) float As[2][BM * ASTRIDE];
    __align__(16) float Bs[2][BK * BN];
};

__device__ __forceinline__ void gemm_inner(const float* __restrict__ As,
                                           const float* __restrict__ Bsr,
                                           int m0, int n0, ull acc2[4][2])
{
    #pragma unroll
    for (int k4 = 0; k4 < BK; k4 += 4) {
        float4 a[4];
        #pragma unroll
        for (int i = 0; i < 4; i++)
            a[i] = *reinterpret_cast<const float4*>(&As[(m0 + i) * ASTRIDE + k4]);
        #pragma unroll
        for (int q = 0; q < 4; q++) {
            float4 bq = *reinterpret_cast<const float4*>(&Bsr[(k4 + q) * BN + n0]);
            ull b01 = pack2(bq.x, bq.y);
            ull b23 = pack2(bq.z, bq.w);
            #pragma unroll
            for (int i = 0; i < 4; i++) {
                const float* af = &a[i].x;
                ull ap = pack2(af[q], af[q]);
                ffma2(acc2[i][0], ap, b01);
                ffma2(acc2[i][1], ap, b23);
            }
        }
    }
}

// epi: 0 none, 1 +bias, 2 +bias->softplus, 3 C += result.
// gridDim.z>1 -> split-K, partials accumulated via atomicAdd (bias ignored).
__global__ void sgemm_k(const float* __restrict__ A, int lda,
                        const float* __restrict__ Bm,
                        float* __restrict__ C,
                        const float* __restrict__ bias,
                        int M, int N, int K, int epi)
{
    __shared__ SmemGemm sm;
    const int bm = blockIdx.y * BM, bn = blockIdx.x * BN;
    const int tid = threadIdx.x;

    const int ksplit = gridDim.z;
    const int kc = K / ksplit;
    const int kstart = blockIdx.z * kc;
    const int kend = kstart + kc;
    const int niters = (kc + BK - 1) / BK;

    const int am  = tid >> 2;
    const int akq = (tid & 3) << 2;
    const int bkb = tid >> 4;
    const int bn4 = (tid & 15) << 2;
    const bool bn_ok = (bn + bn4) < N;

    const float* Arow = A + (size_t)(bm + am) * lda;

    uint32_t sAs = (uint32_t)__cvta_generic_to_shared(&sm.As[0][0]);
    uint32_t sBs = (uint32_t)__cvta_generic_to_shared(&sm.Bs[0][0]);

    auto load_stage = [&](int it, int buf) {
        int k0 = kstart + it * BK;
        {
            int k = k0 + akq;
            bool p = k < kend;
            const float* src = p ? (Arow + k) : A;
            cp_async16(sAs + (buf * BM * ASTRIDE + am * ASTRIDE + akq) * 4, src, p);
        }
        {
            int k = k0 + bkb;
            bool p = (k < kend) && bn_ok;
            const float* src = p ? (Bm + (size_t)k * N + bn + bn4) : Bm;
            cp_async16(sBs + (buf * BK * BN + bkb * BN + bn4) * 4, src, p);
        }
    };

    const int ty = tid >> 4, tx = tid & 15;
    const int m0 = ty * 4, n0 = tx * 4;

    ull acc2[4][2];
    #pragma unroll
    for (int i = 0; i < 4; i++) { acc2[i][0] = 0ull; acc2[i][1] = 0ull; }

    load_stage(0, 0); cp_commit();
    if (niters > 1) load_stage(1, 1);
    cp_commit();

    for (int it = 0; it < niters; it++) {
        cp_wait<1>();
        __syncthreads();
        const int buf = it & 1;
        gemm_inner(&sm.As[buf][0], &sm.Bs[buf][0], m0, n0, acc2);
        __syncthreads();
        if (it + 2 < niters) load_stage(it + 2, buf);
        cp_commit();
    }

    #pragma unroll
    for (int i = 0; i < 4; i++) {
        int row = bm + m0 + i;
        float v[4];
        unpack2(acc2[i][0], v[0], v[1]);
        unpack2(acc2[i][1], v[2], v[3]);
        #pragma unroll
        for (int j = 0; j < 4; j++) {
            int col = bn + n0 + j;
            if (col < N) {
                size_t off = (size_t)row * N + col;
                float vv = v[j];
                if (ksplit > 1) {
                    atomicAdd(&C[off], vv);
                } else {
                    if (epi == 1 || epi == 2) vv += bias[col];
                    if (epi == 2) vv = (vv > 20.f) ? vv : log1pf(__expf(vv));
                    if (epi == 3) vv += C[off];
                    C[off] = vv;
                }
            }
        }
    }
}

// ------------------------- patchify GEMM (im2col fused, split-K) -----------
// Accumulates into pre-zeroed C via atomicAdd; bias added later in posembed.
__global__ void sgemm_patch_k(const float* __restrict__ X,
                              const float* __restrict__ Bm,
                              float* __restrict__ C)
{
    __shared__ SmemGemm sm;
    const int bm = blockIdx.y * BM, bn = blockIdx.x * BN;
    const int tid = threadIdx.x;
    const int N = D;

    const int kc = PATCH_DIM / gridDim.z;
    const int kstart = blockIdx.z * kc;
    const int niters = kc / BK;

    const int am  = tid >> 2;
    const int akq = (tid & 3) << 2;
    const int bkb = tid >> 4;
    const int bn4 = (tid & 15) << 2;

    const int m = bm + am;
    const int b = m >> 10, l = m & 1023;
    const int gh = l >> 6, gw = (l >> 3) & 7, gd = l & 7;
    const size_t xbase = ((size_t)(b * 256 + gh * 16) * 256 + gw * 32) * 64 + gd * 8;

    uint32_t sAs = (uint32_t)__cvta_generic_to_shared(&sm.As[0][0]);
    uint32_t sBs = (uint32_t)__cvta_generic_to_shared(&sm.Bs[0][0]);

    auto load_stage = [&](int it, int buf) {
        int k0 = kstart + it * BK;
        {
            int k = k0 + akq;
            int ph = k >> 8, pw = (k >> 3) & 31, pd = k & 7;
            const float* src = X + xbase + (size_t)ph * 16384 + pw * 64 + pd;
            cp_async16(sAs + (buf * BM * ASTRIDE + am * ASTRIDE + akq) * 4, src, true);
        }
        {
            int k = k0 + bkb;
            const float* src = Bm + (size_t)k * N + bn + bn4;
            cp_async16(sBs + (buf * BK * BN + bkb * BN + bn4) * 4, src, true);
        }
    };

    const int ty = tid >> 4, tx = tid & 15;
    const int m0 = ty * 4, n0 = tx * 4;

    ull acc2[4][2];
    #pragma unroll
    for (int i = 0; i < 4; i++) { acc2[i][0] = 0ull; acc2[i][1] = 0ull; }

    load_stage(0, 0); cp_commit();
    load_stage(1, 1); cp_commit();

    for (int it = 0; it < niters; it++) {
        cp_wait<1>();
        __syncthreads();
        const int buf = it & 1;
        gemm_inner(&sm.As[buf][0], &sm.Bs[buf][0], m0, n0, acc2);
        __syncthreads();
        if (it + 2 < niters) load_stage(it + 2, buf);
        cp_commit();
    }

    #pragma unroll
    for (int i = 0; i < 4; i++) {
        int row = bm + m0 + i;
        float v[4];
        unpack2(acc2[i][0], v[0], v[1]);
        unpack2(acc2[i][1], v[2], v[3]);
        #pragma unroll
        for (int j = 0; j < 4; j++)
            atomicAdd(&C[(size_t)row * N + bn + n0 + j], v[j]);
    }
}

// ------------------------- zero buffer --------------------------------------
__global__ void zero_k(float* __restrict__ p, int n) {
    int i = blockIdx.x * blockDim.x + threadIdx.x;
    if (i < n) p[i] = 0.f;
}

// ------------------------- LayerNorm + xz/dbl zeroing ----------------------
__global__ void ln_k(const float* __restrict__ in, float* __restrict__ out,
                     const float* __restrict__ w, const float* __restrict__ b,
                     float* __restrict__ zdbl, float* __restrict__ zxz)
{
    int row = blockIdx.x;
    int t = threadIdx.x;   // 128 threads
    if (zdbl != nullptr && t < DBL_N) zdbl[(size_t)row * DBL_N + t] = 0.f;
    if (zxz != nullptr) {
        float* zr = zxz + (size_t)row * (2 * D);
        #pragma unroll
        for (int q = 0; q < 6; q++) zr[t + q * 128] = 0.f;
    }
    const float* r = in + (size_t)row * D;
    float v0 = r[t], v1 = r[t + 128], v2 = r[t + 256];
    float s = v0 + v1 + v2;
    __shared__ float sh[4], sh2[4];
    #pragma unroll
    for (int o = 16; o; o >>= 1) s += __shfl_xor_sync(~0u, s, o);
    if ((t & 31) == 0) sh[t >> 5] = s;
    __syncthreads();
    float mu = (sh[0] + sh[1] + sh[2] + sh[3]) * (1.f / 384.f);
    float d0 = v0 - mu, d1 = v1 - mu, d2 = v2 - mu;
    float q = d0 * d0 + d1 * d1 + d2 * d2;
    #pragma unroll
    for (int o = 16; o; o >>= 1) q += __shfl_xor_sync(~0u, q, o);
    if ((t & 31) == 0) sh2[t >> 5] = q;
    __syncthreads();
    float var = (sh2[0] + sh2[1] + sh2[2] + sh2[3]) * (1.f / 384.f);
    float rs = rsqrtf(var + 1e-5f);
    float* o = out + (size_t)row * D;
    o[t]       = d0 * rs * w[t]       + b[t];
    o[t + 128] = d1 * rs * w[t + 128] + b[t + 128];
    o[t + 256] = d2 * rs * w[t + 256] + b[t + 256];
}

// ------------------------- positional embedding + patch bias ---------------
__global__ void posembed_k(const float* __restrict__ bp,
                           const unsigned char* __restrict__ mask,
                           const float* __restrict__ patch_b)
{
    int row = blockIdx.x;           // NTOK
    int d = threadIdx.x;            // 384
    int b = row >> 10, l = row & 1023;
    int gh = l >> 6, gw = (l >> 3) & 7, gd = l & 7;
    float vr = bp[b * 4 + 2];
    bool m = mask[b] != 0;
    int j = d / 128, r = d - j * 128, f = r & 63;
    float c;
    if (j == 0)      c = (float)gh * (1.f / 15.f);
    else if (j == 1) c = ((float)gw - 4.f) * 0.25f;
    else {
        float v = m ? ((float)gd - 4.f) * vr : (float)gd * vr;
        float den = m ? 4.f * vr : 7.f * vr;
        c = v / den;
    }
    float omega = powf(10000.f, -(float)f * (1.f / 64.f));
    float ph = c * omega;
    float pe = (r < 64) ? sinf(ph) : cosf(ph);
    g_tok[(size_t)row * D + d] += pe + patch_b[d];
}

// ------------------------- causal depthwise conv + silu --------------------
__global__ void conv_k(const float* __restrict__ cw, const float* __restrict__ cb)
{
    int row = blockIdx.x;           // NTOK
    int d = threadIdx.x;            // 384
    int l = row & 1023, b = row >> 10;
    float acc = cb[d];
    #pragma unroll
    for (int j = 0; j < 4; j++) {
        int ll = l - 3 + j;
        if (ll >= 0)
            acc = fmaf(g_xz[(size_t)((b << 10) + ll) * (2 * D) + d], cw[d * 4 + j], acc);
    }
    g_xc[(size_t)row * D + d] = acc / (1.f + __expf(-acc));
}

// ------------------------- chunked scan, smem-staged ------------------------
struct ScanTilePart {
    __align__(16) float dt[CHL][SCH];
    __align__(16) float xc[CHL][SCH];
    __align__(16) float bc[CHL][32];   // B[16] | C[16]
};
struct ScanTileFull {
    __align__(16) float dt[CHL][SCH];
    __align__(16) float xc[CHL][SCH];
    __align__(16) float bc[CHL][32];
    __align__(16) float zz[CHL][SCH];
    __align__(16) float yy[CHL][SCH];
};

__device__ __forceinline__ void scan_load_common(
    uint32_t s_dt, uint32_t s_xc, uint32_t s_bc,
    const float* dt_g, const float* xc_g, const float* dbl_b,
    int l0, int d0, int tid)
{
    #pragma unroll
    for (int q = 0; q < 2; q++) {
        int qq = tid + q * 128;
        int row = qq >> 1, part = (qq & 1) << 2;
        cp_async16(s_dt + (row * SCH + part) * 4,
                   dt_g + (size_t)(l0 + row) * D + d0 + part, true);
        cp_async16(s_xc + (row * SCH + part) * 4,
                   xc_g + (size_t)(l0 + row) * D + d0 + part, true);
    }
    #pragma unroll
    for (int q = 0; q < 8; q++) {
        int qq = tid + q * 128;
        int row = qq >> 3, part = (qq & 7) << 2;
        cp_async16(s_bc + (row * 32 + part) * 4,
                   dbl_b + (size_t)(l0 + row) * DBL_N + DTRANK + part, true);
    }
}

__global__ void scan_part_k(const float* __restrict__ A_log)
{
    __shared__ ScanTilePart sm;
    const int tid = threadIdx.x;
    const int grp = tid >> 4, lane = tid & 15;
    const int c = blockIdx.y;
    const int blk = blockIdx.x;             // 0..95
    const int b = blk / 48;
    const int d0 = (blk % 48) * SCH;
    const int d = d0 + grp;
    const int l0 = c * CHL;

    const float* dbl_b = g_dbl + (size_t)b * L * DBL_N;
    scan_load_common((uint32_t)__cvta_generic_to_shared(&sm.dt[0][0]),
                     (uint32_t)__cvta_generic_to_shared(&sm.xc[0][0]),
                     (uint32_t)__cvta_generic_to_shared(&sm.bc[0][0]),
                     g_dt + (size_t)b * L * D, g_xc + (size_t)b * L * D,
                     dbl_b, l0, d0, tid);
    cp_commit();

    const float Aa = -__expf(A_log[d * DSTATE + lane]);

    cp_wait<0>();
    __syncthreads();

    float h = 0.f, P = 1.f;
    #pragma unroll 8
    for (int l = 0; l < CHL; l++) {
        float dtv = sm.dt[l][grp];
        float uv  = sm.xc[l][grp];
        float Bv  = sm.bc[l][lane];
        float dA  = __expf(dtv * Aa);
        h = fmaf(h, dA, dtv * uv * Bv);
        P *= dA;
    }
    const int chain = b * D + d;
    g_P[((size_t)chain * NCH + c) * DSTATE + lane] = P;
    g_W[((size_t)chain * NCH + c) * DSTATE + lane] = h;
}

__global__ void scan_full_k(const float* __restrict__ A_log,
                            const float* __restrict__ Dsk)
{
    __shared__ ScanTileFull sm;
    const int tid = threadIdx.x;
    const int grp = tid >> 4, lane = tid & 15;
    const int c = blockIdx.y;
    const int blk = blockIdx.x;             // 0..95
    const int b = blk / 48;
    const int d0 = (blk % 48) * SCH;
    const int d = d0 + grp;
    const int l0 = c * CHL;

    const float* dbl_b = g_dbl + (size_t)b * L * DBL_N;
    scan_load_common((uint32_t)__cvta_generic_to_shared(&sm.dt[0][0]),
                     (uint32_t)__cvta_generic_to_shared(&sm.xc[0][0]),
                     (uint32_t)__cvta_generic_to_shared(&sm.bc[0][0]),
                     g_dt + (size_t)b * L * D, g_xc + (size_t)b * L * D,
                     dbl_b, l0, d0, tid);
    {
        uint32_t s_zz = (uint32_t)__cvta_generic_to_shared(&sm.zz[0][0]);
        const float* z_g = g_xz + (size_t)b * L * (2 * D) + D;
        #pragma unroll
        for (int q = 0; q < 2; q++) {
            int qq = tid + q * 128;
            int row = qq >> 1, part = (qq & 1) << 2;
            cp_async16(s_zz + (row * SCH + part) * 4,
                       z_g + (size_t)(l0 + row) * (2 * D) + d0 + part, true);
        }
    }
    cp_commit();

    const float Aa = -__expf(A_log[d * DSTATE + lane]);
    const float Dp = __ldg(&Dsk[d]);
    const int chain = b * D + d;

    float h = 0.f;
    const float* Pp = g_P + (size_t)chain * NCH * DSTATE + lane;
    const float* Wp = g_W + (size_t)chain * NCH * DSTATE + lane;
    for (int j = 0; j < c; j++)
        h = fmaf(h, Pp[(size_t)j * DSTATE], Wp[(size_t)j * DSTATE]);

    cp_wait<0>();
    __syncthreads();

    #pragma unroll 8
    for (int l = 0; l < CHL; l++) {
        float dtv = sm.dt[l][grp];
        float uv  = sm.xc[l][grp];
        float Bv  = sm.bc[l][lane];
        float Cv  = sm.bc[l][lane + 16];
        float dA  = __expf(dtv * Aa);
        h = fmaf(h, dA, dtv * uv * Bv);
        float p = h * Cv;
        p += __shfl_xor_sync(0xffffffffu, p, 8);
        p += __shfl_xor_sync(0xffffffffu, p, 4);
        p += __shfl_xor_sync(0xffffffffu, p, 2);
        p += __shfl_xor_sync(0xffffffffu, p, 1);
        if (lane == 0) {
            float zv = sm.zz[l][grp];
            float sz = zv / (1.f + __expf(-zv));
            sm.yy[l][grp] = (p + uv * Dp) * sz;
        }
    }
    __syncthreads();

    float* y_g = g_y + (size_t)(b * L + l0 + tid) * D + d0;
    float4 v0 = *reinterpret_cast<const float4*>(&sm.yy[tid][0]);
    float4 v1 = *reinterpret_cast<const float4*>(&sm.yy[tid][4]);
    *reinterpret_cast<float4*>(y_g)     = v0;
    *reinterpret_cast<float4*>(y_g + 4) = v1;
}

// ------------------------- launch ------------------------------------------
extern "C" void kernel_launch(void* const* d_in, const int* in_sizes, int n_in,
                              void* d_out, int out_size)
{
    const float* x          = (const float*)d_in[0];
    const float* bp         = (const float*)d_in[1];
    const float* patch_w    = (const float*)d_in[2];
    const float* patch_b    = (const float*)d_in[3];
    const float* in_proj_w  = (const float*)d_in[4];
    const float* conv_w     = (const float*)d_in[5];
    const float* conv_b     = (const float*)d_in[6];
    const float* x_proj_w   = (const float*)d_in[7];
    const float* dt_proj_w  = (const float*)d_in[8];
    const float* dt_proj_b  = (const float*)d_in[9];
    const float* A_log      = (const float*)d_in[10];
    const float* Dskip      = (const float*)d_in[11];
    const float* out_proj_w = (const float*)d_in[12];
    const float* norm_w     = (const float*)d_in[13];
    const float* norm_b     = (const float*)d_in[14];
    const float* fw         = (const float*)d_in[15];
    const float* fb         = (const float*)d_in[16];
    const unsigned char* mask = (const unsigned char*)d_in[17];

    float *tok, *h, *xz, *xc, *dbl, *dt, *y;
    cudaGetSymbolAddress((void**)&tok, g_tok);
    cudaGetSymbolAddress((void**)&h,   g_h);
    cudaGetSymbolAddress((void**)&xz,  g_xz);
    cudaGetSymbolAddress((void**)&xc,  g_xc);
    cudaGetSymbolAddress((void**)&dbl, g_dbl);
    cudaGetSymbolAddress((void**)&dt,  g_dt);
    cudaGetSymbolAddress((void**)&y,   g_y);

    // patchify: zero tok, split-K=2 accumulate, bias+posembed fused
    zero_k<<<(NTOK * D + 255) / 256, 256>>>(tok, NTOK * D);
    sgemm_patch_k<<<dim3(D / 64, NTOK / 64, 2), 256>>>(x, patch_w, tok);
    posembed_k<<<NTOK, D>>>(bp, mask, patch_b);

    for (int layer = 0; layer < DEPTH; layer++) {
        ln_k<<<NTOK, 128>>>(tok, h, norm_w + layer * D, norm_b + layer * D, dbl, xz);
        sgemm_k<<<dim3((2 * D) / 64, NTOK / 64, 2), 256>>>(h, D,
                in_proj_w + (size_t)layer * D * 2 * D, xz, nullptr, NTOK, 2 * D, D, 0);
        conv_k<<<NTOK, D>>>(conv_w + (size_t)layer * D * 4, conv_b + (size_t)layer * D);
        sgemm_k<<<dim3(1, NTOK / 64, 4), 256>>>(xc, D,
                x_proj_w + (size_t)layer * D * DBL_N, dbl, nullptr, NTOK, DBL_N, D, 0);
        sgemm_k<<<dim3(D / 64, NTOK / 64, 1), 256>>>(dbl, DBL_N,
                dt_proj_w + (size_t)layer * DTRANK * D, dt, dt_proj_b + (size_t)layer * D,
                NTOK, D, DTRANK, 2);
        scan_part_k<<<dim3(96, NCH), 128>>>(A_log + (size_t)layer * D * DSTATE);
        scan_full_k<<<dim3(96, NCH), 128>>>(A_log + (size_t)layer * D * DSTATE,
                                            Dskip + (size_t)layer * D);
        // out_proj: split-K=2, atomicAdd accumulates residual into tok directly
        sgemm_k<<<dim3(D / 64, NTOK / 64, 2), 256>>>(y, D,
                out_proj_w + (size_t)layer * D * D, tok, nullptr, NTOK, D, D, 3);
    }

    ln_k<<<NTOK, 128>>>(tok, (float*)d_out, fw, fb, nullptr, nullptr);
}